// round 1
// baseline (speedup 1.0000x reference)
#include <cuda_runtime.h>
#include <math.h>

// ---------------- folded-weight scratch (device globals, no allocation) ----
__device__ float g_Wqk0[19 * 32];    // qf(19) -> [A j*4+h (24) | O j*4+h (8)], scale folded
__device__ float g_Wqk1[128 * 32];   // h(128) -> same layout, scale folded
__device__ float g_T0[36 * 128];     // wv^T * pw  (layer0)  t=[A 28 | O 8]
__device__ float g_T1[36 * 128];     // layer1
__device__ float g_W0[36 * 128];     // u0 -> h0  (T0 @ fpw0 selected half)
__device__ float g_TF1[36 * 128];    // u1 -> h1
__device__ float g_b0[128];          // bias of h0
__device__ float g_b1[128];          // bias of h1
__device__ float g_WG1[36 * 32];     // u0 -> G1 directly (W0 @ Wqk1)
__device__ float g_bG1[32];
__device__ float g_Wout[36 * 4];     // u1 -> out directly (TF1 @ headw)
__device__ float g_bout[4];

#define QK_SCALE 0.17677669529663687f   // (C/H)^-0.5 = 1/sqrt(32)

// ---------------- precompute kernels ---------------------------------------
__global__ void pk_qk(const float* __restrict__ wq0, const float* __restrict__ wak0,
                      const float* __restrict__ wok0,
                      const float* __restrict__ wq1, const float* __restrict__ wak1,
                      const float* __restrict__ wok1)
{
    int idx = blockIdx.x * blockDim.x + threadIdx.x;
    if (idx < 19 * 32) {
        int p = idx / 32, t = idx % 32, h = t & 3;
        const float* wk; int j;
        if (t < 24) { j = t >> 2; wk = wak0; } else { j = (t - 24) >> 2; wk = wok0; }
        float s = 0.f;
        for (int c = 0; c < 128; c++)
            s += wq0[p * 512 + h * 128 + c] * wk[j * 512 + h * 128 + c];
        g_Wqk0[idx] = s * QK_SCALE;
    } else if (idx < 19 * 32 + 128 * 32) {
        int i2 = idx - 19 * 32;
        int m = i2 / 32, t = i2 % 32, h = t & 3;
        const float* wk; int j;
        if (t < 24) { j = t >> 2; wk = wak1; } else { j = (t - 24) >> 2; wk = wok1; }
        float s = 0.f;
        for (int c = 0; c < 128; c++)
            s += wq1[m * 512 + h * 128 + c] * wk[j * 512 + h * 128 + c];
        g_Wqk1[i2] = s * QK_SCALE;
    }
}

__global__ void pk_T(const float* __restrict__ wav0, const float* __restrict__ apw0,
                     const float* __restrict__ wov0, const float* __restrict__ opw0,
                     const float* __restrict__ wav1, const float* __restrict__ apw1,
                     const float* __restrict__ wov1, const float* __restrict__ opw1)
{
    int idx = blockIdx.x * blockDim.x + threadIdx.x;
    if (idx >= 2 * 36 * 128) return;
    int L = idx / (36 * 128);
    int r = idx % (36 * 128);
    int t = r / 128, m1 = r % 128, h = t & 3;
    const float* wv; const float* pw; int j;
    if (L == 0) {
        if (t < 28) { wv = wav0; pw = apw0; j = t >> 2; }
        else        { wv = wov0; pw = opw0; j = (t - 28) >> 2; }
    } else {
        if (t < 28) { wv = wav1; pw = apw1; j = t >> 2; }
        else        { wv = wov1; pw = opw1; j = (t - 28) >> 2; }
    }
    float s = 0.f;
    for (int c = 0; c < 128; c++)
        s += wv[j * 512 + h * 128 + c] * pw[(h * 128 + c) * 128 + m1];
    (L == 0 ? g_T0 : g_T1)[r] = s;
}

__global__ void pk_W(const float* __restrict__ fpw0, const float* __restrict__ fpb0,
                     const float* __restrict__ apb0, const float* __restrict__ opb0,
                     const float* __restrict__ fpw1, const float* __restrict__ fpb1,
                     const float* __restrict__ apb1, const float* __restrict__ opb1)
{
    int idx = blockIdx.x * blockDim.x + threadIdx.x;
    if (idx < 4608) {                               // g_W0
        int t = idx / 128, m = idx % 128;
        float s = 0.f;
        for (int m1 = 0; m1 < 128; m1++)
            s += g_T0[t * 128 + m1] * fpw0[((t < 28 ? m1 : 128 + m1)) * 128 + m];
        g_W0[idx] = s;
    } else if (idx < 9216) {                        // g_TF1
        int r = idx - 4608;
        int t = r / 128, m = r % 128;
        float s = 0.f;
        for (int m1 = 0; m1 < 128; m1++)
            s += g_T1[t * 128 + m1] * fpw1[((t < 28 ? m1 : 128 + m1)) * 128 + m];
        g_TF1[r] = s;
    } else if (idx < 9344) {                        // g_b0
        int m = idx - 9216;
        float s = fpb0[m];
        for (int m1 = 0; m1 < 128; m1++)
            s += apb0[m1] * fpw0[m1 * 128 + m] + opb0[m1] * fpw0[(128 + m1) * 128 + m];
        g_b0[m] = s;
    } else if (idx < 9472) {                        // g_b1
        int m = idx - 9344;
        float s = fpb1[m];
        for (int m1 = 0; m1 < 128; m1++)
            s += apb1[m1] * fpw1[m1 * 128 + m] + opb1[m1] * fpw1[(128 + m1) * 128 + m];
        g_b1[m] = s;
    }
}

__global__ void pk_final(const float* __restrict__ headw, const float* __restrict__ headb)
{
    int idx = blockIdx.x * blockDim.x + threadIdx.x;
    if (idx < 1152) {                               // g_WG1 = W0 @ Wqk1
        int t = idx / 32, t2 = idx % 32;
        float s = 0.f;
        for (int m = 0; m < 128; m++)
            s += g_W0[t * 128 + m] * g_Wqk1[m * 32 + t2];
        g_WG1[idx] = s;
    } else if (idx < 1184) {                        // g_bG1 = b0 @ Wqk1
        int t2 = idx - 1152;
        float s = 0.f;
        for (int m = 0; m < 128; m++)
            s += g_b0[m] * g_Wqk1[m * 32 + t2];
        g_bG1[t2] = s;
    } else if (idx < 1328) {                        // g_Wout = TF1 @ headw
        int r = idx - 1184;
        int t = r / 4, o = r % 4;
        float s = 0.f;
        for (int m = 0; m < 128; m++)
            s += g_TF1[t * 128 + m] * headw[m * 4 + o];
        g_Wout[r] = s;
    } else if (idx < 1332) {                        // g_bout = b1 @ headw + headb
        int o = idx - 1328;
        float s = headb[o];
        for (int m = 0; m < 128; m++)
            s += g_b1[m] * headw[m * 4 + o];
        g_bout[o] = s;
    }
}

// ---------------- main per-row kernel ---------------------------------------
__device__ __forceinline__ void attend_pair(
    const float (&G)[32], float ca, float co,
    float ox, float oy,
    const float (&nbv)[2][7], const float (&obf)[2][2],
    float (&u)[36])
{
    // ---- A attention (kfeat = nbv[:,0:6], vfeat = nbv[:,0:7], pos = nbv[:,0:2])
    float lA[2][4];
#pragma unroll
    for (int k = 0; k < 2; k++) {
        float dx = ox - nbv[k][0];
        float dy = oy - nbv[k][1];
        float dw = expf(-ca * sqrtf(dx * dx + dy * dy));
#pragma unroll
        for (int h = 0; h < 4; h++) {
            float d = 0.f;
#pragma unroll
            for (int j = 0; j < 6; j++) d += nbv[k][j] * G[j * 4 + h];
            lA[k][h] = d * dw;
        }
    }
#pragma unroll
    for (int h = 0; h < 4; h++) {
        float m = fmaxf(lA[0][h], lA[1][h]);
        float e0 = expf(lA[0][h] - m), e1 = expf(lA[1][h] - m);
        float inv = 1.f / (e0 + e1);
        float a0 = e0 * inv, a1 = e1 * inv;
#pragma unroll
        for (int j = 0; j < 7; j++)
            u[j * 4 + h] = a0 * nbv[0][j] + a1 * nbv[1][j];
    }
    // ---- O attention (kfeat = vfeat = pos = obf)
    float lO[2][4];
#pragma unroll
    for (int k = 0; k < 2; k++) {
        float dx = ox - obf[k][0];
        float dy = oy - obf[k][1];
        float dw = expf(-co * sqrtf(dx * dx + dy * dy));
#pragma unroll
        for (int h = 0; h < 4; h++) {
            float d = obf[k][0] * G[24 + 0 * 4 + h] + obf[k][1] * G[24 + 1 * 4 + h];
            lO[k][h] = d * dw;
        }
    }
#pragma unroll
    for (int h = 0; h < 4; h++) {
        float m = fmaxf(lO[0][h], lO[1][h]);
        float e0 = expf(lO[0][h] - m), e1 = expf(lO[1][h] - m);
        float inv = 1.f / (e0 + e1);
        float a0 = e0 * inv, a1 = e1 * inv;
#pragma unroll
        for (int j = 0; j < 2; j++)
            u[28 + j * 4 + h] = a0 * obf[0][j] + a1 * obf[1][j];
    }
}

__global__ void __launch_bounds__(128)
actor_main(const float* __restrict__ obs,
           const float* __restrict__ ca0p, const float* __restrict__ co0p,
           const float* __restrict__ ca1p, const float* __restrict__ co1p,
           float* __restrict__ out, int n)
{
    __shared__ __align__(16) float sWqk0[19 * 32];
    __shared__ __align__(16) float sWG1[36 * 32];
    __shared__ __align__(16) float sbG1[32];
    __shared__ __align__(16) float sWout[36 * 4];
    __shared__ float sbout[4];

    int tid = threadIdx.x;
    for (int i = tid; i < 19 * 32; i += 128) sWqk0[i] = g_Wqk0[i];
    for (int i = tid; i < 36 * 32; i += 128) sWG1[i] = g_WG1[i];
    if (tid < 32) sbG1[tid] = g_bG1[tid];
    for (int i = tid; i < 36 * 4; i += 128) sWout[i] = g_Wout[i];
    if (tid < 4) sbout[tid] = g_bout[tid];
    __syncthreads();

    int row = blockIdx.x * 128 + tid;
    if (row >= n) return;
    const float* o = obs + (size_t)row * 37;

    float ca0 = __ldg(ca0p), co0 = __ldg(co0p);
    float ca1 = __ldg(ca1p), co1 = __ldg(co1p);

    float ox = __ldg(o + 0), oy = __ldg(o + 1);
    float nbv[2][7], obf[2][2];
#pragma unroll
    for (int k = 0; k < 2; k++) {
#pragma unroll
        for (int j = 0; j < 6; j++) nbv[k][j] = __ldg(o + 12 + 6 * k + j);
        nbv[k][6] = __ldg(o + 24 + k);
        obf[k][0] = __ldg(o + 26 + 2 * k);
        obf[k][1] = __ldg(o + 27 + 2 * k);
    }

    // ---- layer-0 logit features: G0 = qf @ Wqk0 (scale folded)
    float G0[32];
#pragma unroll
    for (int t = 0; t < 32; t++) G0[t] = 0.f;
#pragma unroll
    for (int p = 0; p < 19; p++) {
        float q = __ldg(o + (p < 12 ? p : p + 18));     // qf = [obs 0:12 | obs 30:37]
        const float4* w = reinterpret_cast<const float4*>(&sWqk0[p * 32]);
#pragma unroll
        for (int t4 = 0; t4 < 8; t4++) {
            float4 ww = w[t4];
            G0[t4 * 4 + 0] += q * ww.x;
            G0[t4 * 4 + 1] += q * ww.y;
            G0[t4 * 4 + 2] += q * ww.z;
            G0[t4 * 4 + 3] += q * ww.w;
        }
    }

    float u0[36];
    attend_pair(G0, ca0, co0, ox, oy, nbv, obf, u0);

    // ---- layer-1 logit features directly: G1 = bG1 + u0 @ WG1 (h0 never materialized)
    float G1[32];
#pragma unroll
    for (int t = 0; t < 32; t++) G1[t] = sbG1[t];
#pragma unroll
    for (int t = 0; t < 36; t++) {
        float uv = u0[t];
        const float4* w = reinterpret_cast<const float4*>(&sWG1[t * 32]);
#pragma unroll
        for (int t4 = 0; t4 < 8; t4++) {
            float4 ww = w[t4];
            G1[t4 * 4 + 0] += uv * ww.x;
            G1[t4 * 4 + 1] += uv * ww.y;
            G1[t4 * 4 + 2] += uv * ww.z;
            G1[t4 * 4 + 3] += uv * ww.w;
        }
    }

    float u1[36];
    attend_pair(G1, ca1, co1, ox, oy, nbv, obf, u1);

    // ---- output directly: out = bout + u1 @ Wout (h1 never materialized)
    float r0 = sbout[0], r1 = sbout[1], r2 = sbout[2], r3 = sbout[3];
#pragma unroll
    for (int t = 0; t < 36; t++) {
        float4 w = reinterpret_cast<const float4*>(sWout)[t];
        r0 += u1[t] * w.x;
        r1 += u1[t] * w.y;
        r2 += u1[t] * w.z;
        r3 += u1[t] * w.w;
    }
    reinterpret_cast<float4*>(out)[row] = make_float4(r0, r1, r2, r3);
}

// ---------------- launch -----------------------------------------------------
extern "C" void kernel_launch(void* const* d_in, const int* in_sizes, int n_in,
                              void* d_out, int out_size)
{
    const float* obs   = (const float*)d_in[0];
    const float* wq0   = (const float*)d_in[1];
    const float* wak0  = (const float*)d_in[2];
    const float* wav0  = (const float*)d_in[3];
    const float* wok0  = (const float*)d_in[4];
    const float* wov0  = (const float*)d_in[5];
    const float* apw0  = (const float*)d_in[6];
    const float* apb0  = (const float*)d_in[7];
    const float* opw0  = (const float*)d_in[8];
    const float* opb0  = (const float*)d_in[9];
    const float* fpw0  = (const float*)d_in[10];
    const float* fpb0  = (const float*)d_in[11];
    const float* ca0   = (const float*)d_in[12];
    const float* co0   = (const float*)d_in[13];
    const float* wq1   = (const float*)d_in[14];
    const float* wak1  = (const float*)d_in[15];
    const float* wav1  = (const float*)d_in[16];
    const float* wok1  = (const float*)d_in[17];
    const float* wov1  = (const float*)d_in[18];
    const float* apw1  = (const float*)d_in[19];
    const float* apb1  = (const float*)d_in[20];
    const float* opw1  = (const float*)d_in[21];
    const float* opb1  = (const float*)d_in[22];
    const float* fpw1  = (const float*)d_in[23];
    const float* fpb1  = (const float*)d_in[24];
    const float* ca1   = (const float*)d_in[25];
    const float* co1   = (const float*)d_in[26];
    const float* headw = (const float*)d_in[27];
    const float* headb = (const float*)d_in[28];

    int n = in_sizes[0] / 37;

    pk_qk   <<<(4704 + 127) / 128, 128>>>(wq0, wak0, wok0, wq1, wak1, wok1);
    pk_T    <<<(9216 + 127) / 128, 128>>>(wav0, apw0, wov0, opw0, wav1, apw1, wov1, opw1);
    pk_W    <<<(9472 + 127) / 128, 128>>>(fpw0, fpb0, apb0, opb0, fpw1, fpb1, apb1, opb1);
    pk_final<<<(1332 + 127) / 128, 128>>>(headw, headb);

    actor_main<<<(n + 127) / 128, 128>>>(obs, ca0, co0, ca1, co1, (float*)d_out, n);
}

// round 2
// speedup vs baseline: 1.3228x; 1.3228x over previous
#include <cuda_runtime.h>
#include <math.h>

// ---------------- folded-weight scratch (device globals) -------------------
__device__ float g_Wqk0[19 * 32];
__device__ float g_Wqk1[128 * 32];
__device__ float g_T0[36 * 128];
__device__ float g_T1[36 * 128];
__device__ float g_b0[128];
__device__ float g_b1[128];
__device__ float g_WG1[36 * 32];
__device__ float g_bG1[32];
__device__ float g_Wout[36 * 4];
__device__ float g_bout[4];

#define QK_SCALE 0.17677669529663687f   // 1/sqrt(32)

// ---------------- packed f32x2 helpers --------------------------------------
struct f2 { unsigned long long v; };

__device__ __forceinline__ f2 mkf2(float lo, float hi) {
    f2 r; asm("mov.b64 %0,{%1,%2};" : "=l"(r.v) : "f"(lo), "f"(hi)); return r;
}
__device__ __forceinline__ void unf2(f2 a, float& lo, float& hi) {
    asm("mov.b64 {%0,%1},%2;" : "=f"(lo), "=f"(hi) : "l"(a.v));
}
__device__ __forceinline__ f2 ffma2(f2 a, f2 b, f2 c) {
    f2 r; asm("fma.rn.f32x2 %0,%1,%2,%3;" : "=l"(r.v) : "l"(a.v), "l"(b.v), "l"(c.v)); return r;
}
__device__ __forceinline__ f2 fmul2(f2 a, f2 b) {
    f2 r; asm("mul.rn.f32x2 %0,%1,%2;" : "=l"(r.v) : "l"(a.v), "l"(b.v)); return r;
}
__device__ __forceinline__ f2 fadd2(f2 a, f2 b) {
    f2 r; asm("add.rn.f32x2 %0,%1,%2;" : "=l"(r.v) : "l"(a.v), "l"(b.v)); return r;
}
__device__ __forceinline__ f2 expv(f2 a) {
    float l, h; unf2(a, l, h);
    return mkf2(__expf(l), __expf(h));
}
__device__ __forceinline__ f2 rcpv(f2 a) {
    float l, h; unf2(a, l, h);
    float rl, rh;
    asm("rcp.approx.f32 %0,%1;" : "=f"(rl) : "f"(l));
    asm("rcp.approx.f32 %0,%1;" : "=f"(rh) : "f"(h));
    return mkf2(rl, rh);
}

// ---------------- precompute kernel 1 (inputs -> Wqk0, Wqk1, T0, T1, b0, b1)
__global__ void pk1(const float* __restrict__ wq0, const float* __restrict__ wak0,
                    const float* __restrict__ wok0,
                    const float* __restrict__ wq1, const float* __restrict__ wak1,
                    const float* __restrict__ wok1,
                    const float* __restrict__ wav0, const float* __restrict__ apw0,
                    const float* __restrict__ wov0, const float* __restrict__ opw0,
                    const float* __restrict__ wav1, const float* __restrict__ apw1,
                    const float* __restrict__ wov1, const float* __restrict__ opw1,
                    const float* __restrict__ fpb0, const float* __restrict__ apb0,
                    const float* __restrict__ opb0,
                    const float* __restrict__ fpb1, const float* __restrict__ apb1,
                    const float* __restrict__ opb1,
                    const float* __restrict__ fpw0, const float* __restrict__ fpw1)
{
    int bid = blockIdx.x, tid = threadIdx.x;
    if (bid < 72) {
        // T rows: one block per (layer, t), threads over m1 (coalesced pw column walk)
        int L = bid / 36, t = bid % 36, h = t & 3;
        const float* wv; const float* pw; int j;
        if (L == 0) {
            if (t < 28) { wv = wav0; pw = apw0; j = t >> 2; }
            else        { wv = wov0; pw = opw0; j = (t - 28) >> 2; }
        } else {
            if (t < 28) { wv = wav1; pw = apw1; j = t >> 2; }
            else        { wv = wov1; pw = opw1; j = (t - 28) >> 2; }
        }
        __shared__ float swv[128];
        swv[tid] = wv[j * 512 + h * 128 + tid];
        __syncthreads();
        const float* pwb = pw + h * 128 * 128 + tid;
        float a0 = 0.f, a1 = 0.f, a2 = 0.f, a3 = 0.f;
#pragma unroll 8
        for (int c = 0; c < 128; c += 4) {
            a0 += swv[c + 0] * pwb[(c + 0) * 128];
            a1 += swv[c + 1] * pwb[(c + 1) * 128];
            a2 += swv[c + 2] * pwb[(c + 2) * 128];
            a3 += swv[c + 3] * pwb[(c + 3) * 128];
        }
        (L == 0 ? g_T0 : g_T1)[t * 128 + tid] = (a0 + a1) + (a2 + a3);
    } else if (bid < 91) {
        // Wqk0 row p: warp-per-output dot reductions
        int p = bid - 72;
        int wid = tid >> 5, lane = tid & 31, h = wid;
        const float4 a = *(const float4*)(wq0 + p * 512 + h * 128 + lane * 4);
#pragma unroll
        for (int i = 0; i < 8; i++) {
            int t = wid + 4 * i;
            const float* wk; int j;
            if (t < 24) { wk = wak0; j = i; } else { wk = wok0; j = i - 6; }
            const float4 b = *(const float4*)(wk + j * 512 + h * 128 + lane * 4);
            float s = a.x * b.x + a.y * b.y + a.z * b.z + a.w * b.w;
#pragma unroll
            for (int off = 16; off; off >>= 1) s += __shfl_xor_sync(0xffffffffu, s, off);
            if (lane == 0) g_Wqk0[p * 32 + t] = s * QK_SCALE;
        }
    } else if (bid < 219) {
        // Wqk1 row m
        int m = bid - 91;
        int wid = tid >> 5, lane = tid & 31, h = wid;
        const float4 a = *(const float4*)(wq1 + m * 512 + h * 128 + lane * 4);
#pragma unroll
        for (int i = 0; i < 8; i++) {
            int t = wid + 4 * i;
            const float* wk; int j;
            if (t < 24) { wk = wak1; j = i; } else { wk = wok1; j = i - 6; }
            const float4 b = *(const float4*)(wk + j * 512 + h * 128 + lane * 4);
            float s = a.x * b.x + a.y * b.y + a.z * b.z + a.w * b.w;
#pragma unroll
            for (int off = 16; off; off >>= 1) s += __shfl_xor_sync(0xffffffffu, s, off);
            if (lane == 0) g_Wqk1[m * 32 + t] = s * QK_SCALE;
        }
    } else if (bid == 219) {
        float s = fpb0[tid];
#pragma unroll 4
        for (int m1 = 0; m1 < 128; m1++)
            s += apb0[m1] * fpw0[m1 * 128 + tid] + opb0[m1] * fpw0[(128 + m1) * 128 + tid];
        g_b0[tid] = s;
    } else {
        float s = fpb1[tid];
#pragma unroll 4
        for (int m1 = 0; m1 < 128; m1++)
            s += apb1[m1] * fpw1[m1 * 128 + tid] + opb1[m1] * fpw1[(128 + m1) * 128 + tid];
        g_b1[tid] = s;
    }
}

// ---------------- precompute kernel 2 (T,b,Wqk1 -> WG1, Wout, bG1, bout) ----
__global__ void pk2(const float* __restrict__ fpw0, const float* __restrict__ fpw1,
                    const float* __restrict__ headw, const float* __restrict__ headb)
{
    int bid = blockIdx.x, tid = threadIdx.x;
    __shared__ float sT[128];
    __shared__ float sW[128];
    if (bid < 72) {
        int which = bid / 36, t = bid % 36;
        const float* gT  = which ? g_T1 : g_T0;
        const float* fpw = which ? fpw1 : fpw0;
        sT[tid] = gT[t * 128 + tid];
        __syncthreads();
        const float* base = fpw + (t < 28 ? 0 : 128 * 128) + tid;
        float a0 = 0.f, a1 = 0.f, a2 = 0.f, a3 = 0.f;
#pragma unroll 8
        for (int m1 = 0; m1 < 128; m1 += 4) {
            a0 += sT[m1 + 0] * base[(m1 + 0) * 128];
            a1 += sT[m1 + 1] * base[(m1 + 1) * 128];
            a2 += sT[m1 + 2] * base[(m1 + 2) * 128];
            a3 += sT[m1 + 3] * base[(m1 + 3) * 128];
        }
        sW[tid] = (a0 + a1) + (a2 + a3);
        __syncthreads();
        if (which == 0) {
            if (tid < 32) {
                float s0 = 0.f, s1 = 0.f;
#pragma unroll 8
                for (int m = 0; m < 128; m += 2) {
                    s0 += sW[m]     * g_Wqk1[m * 32 + tid];
                    s1 += sW[m + 1] * g_Wqk1[(m + 1) * 32 + tid];
                }
                g_WG1[t * 32 + tid] = s0 + s1;
            }
        } else {
            if (tid < 4) {
                float s0 = 0.f, s1 = 0.f;
#pragma unroll 8
                for (int m = 0; m < 128; m += 2) {
                    s0 += sW[m]     * headw[m * 4 + tid];
                    s1 += sW[m + 1] * headw[(m + 1) * 4 + tid];
                }
                g_Wout[t * 4 + tid] = s0 + s1;
            }
        }
    } else if (bid == 72) {
        if (tid < 32) {
            float s = 0.f;
#pragma unroll 8
            for (int m = 0; m < 128; m++) s += g_b0[m] * g_Wqk1[m * 32 + tid];
            g_bG1[tid] = s;
        }
    } else {
        if (tid < 4) {
            float s = headb[tid];
#pragma unroll 8
            for (int m = 0; m < 128; m++) s += g_b1[m] * headw[m * 4 + tid];
            g_bout[tid] = s;
        }
    }
}

// ---------------- main per-row-pair kernel -----------------------------------
// Computes logits from G, softmax, and streams u directly into ACC (width W),
// so u and h are never materialized.
template <int W>
__device__ __forceinline__ void attend_consume(
    const f2 (&G)[32], const f2 (&dwA)[2], const f2 (&dwO)[2],
    const f2 (&nbv)[2][7], const f2 (&obf)[2][2],
    const f2* __restrict__ wtab, const f2* __restrict__ bias, f2 (&ACC)[W])
{
    f2 lA[2][4], lO[2][4];
#pragma unroll
    for (int k = 0; k < 2; k++) {
#pragma unroll
        for (int h = 0; h < 4; h++) {
            f2 d = fmul2(nbv[k][0], G[h]);
#pragma unroll
            for (int j = 1; j < 6; j++) d = ffma2(nbv[k][j], G[j * 4 + h], d);
            lA[k][h] = fmul2(d, dwA[k]);
            f2 e = ffma2(obf[k][1], G[28 + h], fmul2(obf[k][0], G[24 + h]));
            lO[k][h] = fmul2(e, dwO[k]);
        }
    }
#pragma unroll
    for (int t = 0; t < W; t++) ACC[t] = bias[t];
#pragma unroll
    for (int h = 0; h < 4; h++) {
        {
            f2 e0 = expv(lA[0][h]), e1 = expv(lA[1][h]);
            f2 inv = rcpv(fadd2(e0, e1));
            f2 a0 = fmul2(e0, inv), a1 = fmul2(e1, inv);
#pragma unroll
            for (int j = 0; j < 7; j++) {
                f2 uv = ffma2(a1, nbv[1][j], fmul2(a0, nbv[0][j]));
                const f2* row = wtab + (j * 4 + h) * W;
#pragma unroll
                for (int t = 0; t < W; t += 2) {
                    ulonglong2 wp = *(const ulonglong2*)(row + t);
                    ACC[t]     = ffma2(uv, f2{wp.x}, ACC[t]);
                    ACC[t + 1] = ffma2(uv, f2{wp.y}, ACC[t + 1]);
                }
            }
        }
        {
            f2 e0 = expv(lO[0][h]), e1 = expv(lO[1][h]);
            f2 inv = rcpv(fadd2(e0, e1));
            f2 a0 = fmul2(e0, inv), a1 = fmul2(e1, inv);
#pragma unroll
            for (int j = 0; j < 2; j++) {
                f2 uv = ffma2(a1, obf[1][j], fmul2(a0, obf[0][j]));
                const f2* row = wtab + (28 + j * 4 + h) * W;
#pragma unroll
                for (int t = 0; t < W; t += 2) {
                    ulonglong2 wp = *(const ulonglong2*)(row + t);
                    ACC[t]     = ffma2(uv, f2{wp.x}, ACC[t]);
                    ACC[t + 1] = ffma2(uv, f2{wp.y}, ACC[t + 1]);
                }
            }
        }
    }
}

// dynamic smem layout
#define SM_OBS_F     (256 * 37)          // 9472 floats
#define SM_OBS_B     (SM_OBS_F * 4)      // 37888
#define SM_WQK0_OFF  SM_OBS_B            // 608 f2 = 4864
#define SM_WG1_OFF   (SM_WQK0_OFF + 608 * 8)   // 42752, 1152 f2 = 9216
#define SM_WOUT_OFF  (SM_WG1_OFF + 1152 * 8)   // 51968, 144 f2 = 1152
#define SM_BG1_OFF   (SM_WOUT_OFF + 144 * 8)   // 53120, 32 f2 = 256
#define SM_BOUT_OFF  (SM_BG1_OFF + 32 * 8)     // 53376, 4 f2 = 32
#define SM_TOTAL     (SM_BOUT_OFF + 4 * 8)     // 53408

__global__ void __launch_bounds__(128)
actor_main(const float* __restrict__ obs,
           const float* __restrict__ ca0p, const float* __restrict__ co0p,
           const float* __restrict__ ca1p, const float* __restrict__ co1p,
           float* __restrict__ out, int n)
{
    extern __shared__ __align__(16) unsigned char smbuf[];
    float* sObs  = (float*)smbuf;
    f2* sWqk0 = (f2*)(smbuf + SM_WQK0_OFF);
    f2* sWG1  = (f2*)(smbuf + SM_WG1_OFF);
    f2* sWout = (f2*)(smbuf + SM_WOUT_OFF);
    f2* sbG1  = (f2*)(smbuf + SM_BG1_OFF);
    f2* sbout = (f2*)(smbuf + SM_BOUT_OFF);

    int tid = threadIdx.x;

    // ---- stage 256 rows of obs via coalesced float4 ----
    {
        long nel = (long)n * 37;
        long eb  = (long)blockIdx.x * 9472;
        const float4* g4 = (const float4*)obs;
        float4* s4 = (float4*)sObs;
#pragma unroll 4
        for (int i = tid; i < 2368; i += 128) {
            long e = eb + (long)i * 4;
            if (e + 3 < nel) {
                s4[i] = g4[eb / 4 + i];
            } else {
#pragma unroll
                for (int k = 0; k < 4; k++)
                    sObs[i * 4 + k] = (e + k < nel) ? obs[e + k] : 0.f;
            }
        }
    }
    // ---- stage duplicated-pair weights ----
    for (int i = tid; i < 608;  i += 128) { float w = g_Wqk0[i]; sWqk0[i] = mkf2(w, w); }
    for (int i = tid; i < 1152; i += 128) { float w = g_WG1[i];  sWG1[i]  = mkf2(w, w); }
    for (int i = tid; i < 144;  i += 128) { float w = g_Wout[i]; sWout[i] = mkf2(w, w); }
    if (tid < 32) { float w = g_bG1[tid];  sbG1[tid]  = mkf2(w, w); }
    if (tid < 4)  { float w = g_bout[tid]; sbout[tid] = mkf2(w, w); }
    __syncthreads();

    int r0 = blockIdx.x * 256 + tid;
    if (r0 >= n) return;
    int r1 = r0 + 128;
    const float* lo = &sObs[tid * 37];
    const float* hi = &sObs[(tid + 128) * 37];

    float nca0 = -__ldg(ca0p), nco0 = -__ldg(co0p);
    float nca1 = -__ldg(ca1p), nco1 = -__ldg(co1p);

    // ---- gather per-row features ----
    f2 nbv[2][7], obf[2][2];
#pragma unroll
    for (int k = 0; k < 2; k++) {
#pragma unroll
        for (int j = 0; j < 6; j++) nbv[k][j] = mkf2(lo[12 + 6 * k + j], hi[12 + 6 * k + j]);
        nbv[k][6] = mkf2(lo[24 + k], hi[24 + k]);
        obf[k][0] = mkf2(lo[26 + 2 * k], hi[26 + 2 * k]);
        obf[k][1] = mkf2(lo[27 + 2 * k], hi[27 + 2 * k]);
    }

    // ---- distances (same for both layers), then per-layer decay weights ----
    float dAl[2], dAh[2], dOl[2], dOh[2];
    {
        float axl = lo[0], ayl = lo[1], axh = hi[0], ayh = hi[1];
#pragma unroll
        for (int k = 0; k < 2; k++) {
            float dx = axl - lo[12 + 6 * k], dy = ayl - lo[13 + 6 * k];
            dAl[k] = sqrtf(dx * dx + dy * dy);
            dx = axh - hi[12 + 6 * k]; dy = ayh - hi[13 + 6 * k];
            dAh[k] = sqrtf(dx * dx + dy * dy);
            dx = axl - lo[26 + 2 * k]; dy = ayl - lo[27 + 2 * k];
            dOl[k] = sqrtf(dx * dx + dy * dy);
            dx = axh - hi[26 + 2 * k]; dy = ayh - hi[27 + 2 * k];
            dOh[k] = sqrtf(dx * dx + dy * dy);
        }
    }
    f2 dwA0[2], dwO0[2], dwA1[2], dwO1[2];
#pragma unroll
    for (int k = 0; k < 2; k++) {
        dwA0[k] = mkf2(__expf(nca0 * dAl[k]), __expf(nca0 * dAh[k]));
        dwO0[k] = mkf2(__expf(nco0 * dOl[k]), __expf(nco0 * dOh[k]));
        dwA1[k] = mkf2(__expf(nca1 * dAl[k]), __expf(nca1 * dAh[k]));
        dwO1[k] = mkf2(__expf(nco1 * dOl[k]), __expf(nco1 * dOh[k]));
    }

    // ---- layer-0 logit features: G0 = qf @ Wqk0 ----
    f2 G[32];
#pragma unroll
    for (int t = 0; t < 32; t++) G[t] = f2{0ull};
#pragma unroll
    for (int p = 0; p < 19; p++) {
        int src = (p < 12) ? p : p + 18;
        f2 q = mkf2(lo[src], hi[src]);
        const f2* row = sWqk0 + p * 32;
#pragma unroll
        for (int t = 0; t < 32; t += 2) {
            ulonglong2 wp = *(const ulonglong2*)(row + t);
            G[t]     = ffma2(q, f2{wp.x}, G[t]);
            G[t + 1] = ffma2(q, f2{wp.y}, G[t + 1]);
        }
    }

    // ---- layer 0 attention -> G1 directly ----
    f2 G1[32];
    attend_consume<32>(G, dwA0, dwO0, nbv, obf, sWG1, sbG1, G1);

    // ---- layer 1 attention -> output directly ----
    f2 R[4];
    attend_consume<4>(G1, dwA1, dwO1, nbv, obf, sWout, sbout, R);

    float o0l, o0h, o1l, o1h, o2l, o2h, o3l, o3h;
    unf2(R[0], o0l, o0h); unf2(R[1], o1l, o1h);
    unf2(R[2], o2l, o2h); unf2(R[3], o3l, o3h);
    ((float4*)out)[r0] = make_float4(o0l, o1l, o2l, o3l);
    if (r1 < n) ((float4*)out)[r1] = make_float4(o0h, o1h, o2h, o3h);
}

// ---------------- launch -----------------------------------------------------
extern "C" void kernel_launch(void* const* d_in, const int* in_sizes, int n_in,
                              void* d_out, int out_size)
{
    const float* obs   = (const float*)d_in[0];
    const float* wq0   = (const float*)d_in[1];
    const float* wak0  = (const float*)d_in[2];
    const float* wav0  = (const float*)d_in[3];
    const float* wok0  = (const float*)d_in[4];
    const float* wov0  = (const float*)d_in[5];
    const float* apw0  = (const float*)d_in[6];
    const float* apb0  = (const float*)d_in[7];
    const float* opw0  = (const float*)d_in[8];
    const float* opb0  = (const float*)d_in[9];
    const float* fpw0  = (const float*)d_in[10];
    const float* fpb0  = (const float*)d_in[11];
    const float* ca0   = (const float*)d_in[12];
    const float* co0   = (const float*)d_in[13];
    const float* wq1   = (const float*)d_in[14];
    const float* wak1  = (const float*)d_in[15];
    const float* wav1  = (const float*)d_in[16];
    const float* wok1  = (const float*)d_in[17];
    const float* wov1  = (const float*)d_in[18];
    const float* apw1  = (const float*)d_in[19];
    const float* apb1  = (const float*)d_in[20];
    const float* opb1  = (const float*)d_in[21];
    const float* opw1  = (const float*)d_in[22];   // NOTE: order per metadata below
    const float* fpw1  = (const float*)d_in[23];
    const float* fpb1  = (const float*)d_in[24];
    const float* ca1   = (const float*)d_in[25];
    const float* co1   = (const float*)d_in[26];
    const float* headw = (const float*)d_in[27];
    const float* headb = (const float*)d_in[28];

    // metadata order is setup_inputs order: obs, wq0, wak0, wav0, wok0, wov0,
    // apw0, apb0, opw0, opb0, fpw0, fpb0, ca0, co0, wq1, wak1, wav1, wok1,
    // wov1, apw1, apb1, opw1, opb1, fpw1, fpb1, ca1, co1, headw, headb
    // (fix the two swapped above to match exactly)
    const float* apw1_ = (const float*)d_in[19];
    const float* apb1_ = (const float*)d_in[20];
    const float* opw1_ = (const float*)d_in[21];
    const float* opb1_ = (const float*)d_in[22];
    apw1 = apw1_; apb1 = apb1_; opw1 = opw1_; opb1 = opb1_;

    int n = in_sizes[0] / 37;

    pk1<<<221, 128>>>(wq0, wak0, wok0, wq1, wak1, wok1,
                      wav0, apw0, wov0, opw0, wav1, apw1, wov1, opw1,
                      fpb0, apb0, opb0, fpb1, apb1, opb1, fpw0, fpw1);
    pk2<<<74, 128>>>(fpw0, fpw1, headw, headb);

    cudaFuncSetAttribute(actor_main, cudaFuncAttributeMaxDynamicSharedMemorySize, SM_TOTAL);
    int grid = (n + 255) / 256;
    actor_main<<<grid, 128, SM_TOTAL>>>(obs, ca0, co0, ca1, co1, (float*)d_out, n);
}

// round 3
// speedup vs baseline: 1.4780x; 1.1174x over previous
#include <cuda_runtime.h>
#include <math.h>

// ---------------- folded-weight scratch (device globals) -------------------
__device__ float g_Wqk0[19 * 32];
__device__ float g_Wqk1[128 * 32];
__device__ float g_T0[36 * 128];
__device__ float g_T1[36 * 128];
__device__ float g_b0[128];
__device__ float g_b1[128];
__device__ float g_WG1[36 * 32];
__device__ float g_bG1[32];
__device__ float g_Wout[36 * 4];
__device__ float g_bout[4];

#define QK_SCALE 0.17677669529663687f   // 1/sqrt(32)

// ---------------- packed f32x2 helpers --------------------------------------
struct f2 { unsigned long long v; };

__device__ __forceinline__ f2 mkf2(float lo, float hi) {
    f2 r; asm("mov.b64 %0,{%1,%2};" : "=l"(r.v) : "f"(lo), "f"(hi)); return r;
}
__device__ __forceinline__ void unf2(f2 a, float& lo, float& hi) {
    asm("mov.b64 {%0,%1},%2;" : "=f"(lo), "=f"(hi) : "l"(a.v));
}
__device__ __forceinline__ f2 ffma2(f2 a, f2 b, f2 c) {
    f2 r; asm("fma.rn.f32x2 %0,%1,%2,%3;" : "=l"(r.v) : "l"(a.v), "l"(b.v), "l"(c.v)); return r;
}
__device__ __forceinline__ f2 fmul2(f2 a, f2 b) {
    f2 r; asm("mul.rn.f32x2 %0,%1,%2;" : "=l"(r.v) : "l"(a.v), "l"(b.v)); return r;
}
__device__ __forceinline__ f2 fadd2(f2 a, f2 b) {
    f2 r; asm("add.rn.f32x2 %0,%1,%2;" : "=l"(r.v) : "l"(a.v), "l"(b.v)); return r;
}
__device__ __forceinline__ f2 expv(f2 a) {
    float l, h; unf2(a, l, h);
    return mkf2(__expf(l), __expf(h));
}
__device__ __forceinline__ f2 rcpv(f2 a) {
    float l, h; unf2(a, l, h);
    float rl, rh;
    asm("rcp.approx.f32 %0,%1;" : "=f"(rl) : "f"(l));
    asm("rcp.approx.f32 %0,%1;" : "=f"(rh) : "f"(h));
    return mkf2(rl, rh);
}

// ---------------- precompute kernel 1 ----------------------------------------
// bid [0,72):   T rows       (512 thr: 4-way split of 128-deep reduction)
// bid [72,219): Wqk rows     (512 thr: 32 outputs x 16 lanes x 8 c)
// bid 219/220:  b0/b1        (512 thr: 4-way split of 2x128-deep reduction)
__global__ void __launch_bounds__(512)
pk1(const float* __restrict__ wq0, const float* __restrict__ wak0,
    const float* __restrict__ wok0,
    const float* __restrict__ wq1, const float* __restrict__ wak1,
    const float* __restrict__ wok1,
    const float* __restrict__ wav0, const float* __restrict__ apw0,
    const float* __restrict__ wov0, const float* __restrict__ opw0,
    const float* __restrict__ wav1, const float* __restrict__ apw1,
    const float* __restrict__ wov1, const float* __restrict__ opw1,
    const float* __restrict__ fpb0, const float* __restrict__ apb0,
    const float* __restrict__ opb0,
    const float* __restrict__ fpb1, const float* __restrict__ apb1,
    const float* __restrict__ opb1,
    const float* __restrict__ fpw0, const float* __restrict__ fpw1)
{
    __shared__ float sh[512];
    __shared__ float svec[128];
    int bid = blockIdx.x, tid = threadIdx.x;

    if (bid < 72) {
        int L = bid / 36, t = bid % 36, h = t & 3;
        const float* wv; const float* pw; int j;
        if (L == 0) {
            if (t < 28) { wv = wav0; pw = apw0; j = t >> 2; }
            else        { wv = wov0; pw = opw0; j = (t - 28) >> 2; }
        } else {
            if (t < 28) { wv = wav1; pw = apw1; j = t >> 2; }
            else        { wv = wov1; pw = opw1; j = (t - 28) >> 2; }
        }
        if (tid < 128) svec[tid] = wv[j * 512 + h * 128 + tid];
        __syncthreads();
        int q = tid >> 7, m = tid & 127;
        const float* base = pw + h * 16384 + q * 32 * 128 + m;
        float s = 0.f;
#pragma unroll
        for (int i = 0; i < 32; i++)
            s += svec[q * 32 + i] * base[i * 128];
        sh[tid] = s;
        __syncthreads();
        if (tid < 128)
            (L ? g_T1 : g_T0)[t * 128 + tid] =
                (sh[tid] + sh[tid + 128]) + (sh[tid + 256] + sh[tid + 384]);
    } else if (bid < 219) {
        int r = bid - 72;
        const float* wq; const float* wak; const float* wok; float* dst; int rowoff;
        if (r < 19) { wq = wq0; wak = wak0; wok = wok0; dst = g_Wqk0 + r * 32; rowoff = r * 512; }
        else { r -= 19; wq = wq1; wak = wak1; wok = wok1; dst = g_Wqk1 + r * 32; rowoff = r * 512; }
        int t = tid >> 4, ci = tid & 15, h = t & 3;
        const float* wk; int j;
        if (t < 24) { wk = wak; j = t >> 2; } else { wk = wok; j = (t - 24) >> 2; }
        const float4* a4 = (const float4*)(wq + rowoff + h * 128 + ci * 8);
        const float4* b4 = (const float4*)(wk + j * 512 + h * 128 + ci * 8);
        float4 a0 = a4[0], a1 = a4[1], b0 = b4[0], b1 = b4[1];
        float s = a0.x * b0.x + a0.y * b0.y + a0.z * b0.z + a0.w * b0.w
                + a1.x * b1.x + a1.y * b1.y + a1.z * b1.z + a1.w * b1.w;
#pragma unroll
        for (int off = 8; off; off >>= 1) s += __shfl_xor_sync(0xffffffffu, s, off);
        if (ci == 0) dst[t] = s * QK_SCALE;
    } else {
        const float* fpb; const float* apb; const float* opb; const float* fpw; float* gb;
        if (bid == 219) { fpb = fpb0; apb = apb0; opb = opb0; fpw = fpw0; gb = g_b0; }
        else            { fpb = fpb1; apb = apb1; opb = opb1; fpw = fpw1; gb = g_b1; }
        int q = tid >> 7, m = tid & 127;
        float s = 0.f;
#pragma unroll
        for (int i = 0; i < 32; i++) {
            int m1 = q * 32 + i;
            s += apb[m1] * fpw[m1 * 128 + m] + opb[m1] * fpw[(128 + m1) * 128 + m];
        }
        sh[tid] = s;
        __syncthreads();
        if (tid < 128)
            gb[tid] = fpb[tid] + (sh[tid] + sh[tid + 128]) + (sh[tid + 256] + sh[tid + 384]);
    }
}

// ---------------- precompute kernel 2 ----------------------------------------
// bid [0,72): (which,t): sW = T @ fpw (4-way), then WG1 row / Wout row
// bid 72: bG1, bid 73: bout
__global__ void __launch_bounds__(512)
pk2(const float* __restrict__ fpw0, const float* __restrict__ fpw1,
    const float* __restrict__ headw, const float* __restrict__ headb)
{
    __shared__ float sh[512];
    __shared__ float sT[128], sW[128];
    int bid = blockIdx.x, tid = threadIdx.x;

    if (bid < 72) {
        int which = bid / 36, t = bid % 36;
        const float* gT  = which ? g_T1 : g_T0;
        const float* fpw = which ? fpw1 : fpw0;
        if (tid < 128) sT[tid] = gT[t * 128 + tid];
        __syncthreads();
        int q = tid >> 7, m = tid & 127;
        const float* base = fpw + (t < 28 ? 0 : 16384) + q * 32 * 128 + m;
        float s = 0.f;
#pragma unroll
        for (int i = 0; i < 32; i++)
            s += sT[q * 32 + i] * base[i * 128];
        sh[tid] = s;
        __syncthreads();
        if (tid < 128)
            sW[tid] = (sh[tid] + sh[tid + 128]) + (sh[tid + 256] + sh[tid + 384]);
        __syncthreads();
        if (which == 0) {
            // WG1[t, t2] = sum_m sW[m] * g_Wqk1[m*32 + t2]
            int t2 = tid >> 4, mi = tid & 15;
            float s2 = 0.f;
#pragma unroll
            for (int i = 0; i < 8; i++) {
                int m2 = mi * 8 + i;
                s2 += sW[m2] * g_Wqk1[m2 * 32 + t2];
            }
#pragma unroll
            for (int off = 8; off; off >>= 1) s2 += __shfl_xor_sync(0xffffffffu, s2, off);
            if (mi == 0) g_WG1[t * 32 + t2] = s2;
        } else {
            // Wout[t, o] = sum_m sW[m] * headw[m*4 + o]
            if (tid < 128) {
                float w0 = sW[tid];
                float4 hw = *(const float4*)(headw + tid * 4);
                sh[tid]       = w0 * hw.x;
                sh[tid + 128] = w0 * hw.y;
                sh[tid + 256] = w0 * hw.z;
                sh[tid + 384] = w0 * hw.w;
            }
            __syncthreads();
            int w = tid >> 5, lane = tid & 31;
            if (w < 4) {
                float s2 = sh[w * 128 + lane] + sh[w * 128 + lane + 32]
                         + sh[w * 128 + lane + 64] + sh[w * 128 + lane + 96];
#pragma unroll
                for (int off = 16; off; off >>= 1) s2 += __shfl_xor_sync(0xffffffffu, s2, off);
                if (lane == 0) g_Wout[t * 4 + w] = s2;
            }
        }
    } else if (bid == 72) {
        // bG1[t2] = sum_m g_b0[m] * g_Wqk1[m*32 + t2]
        int t2 = tid & 31, mq = tid >> 5;   // 16 groups x 8 m
        float s = 0.f;
#pragma unroll
        for (int i = 0; i < 8; i++) {
            int m = mq * 8 + i;
            s += g_b0[m] * g_Wqk1[m * 32 + t2];
        }
        sh[tid] = s;
        __syncthreads();
        if (tid < 32) {
            float s2 = 0.f;
#pragma unroll
            for (int g = 0; g < 16; g++) s2 += sh[g * 32 + tid];
            g_bG1[tid] = s2;
        }
    } else {
        // bout[o] = headb[o] + sum_m g_b1[m] * headw[m*4 + o]
        if (tid < 128) {
            float b = g_b1[tid];
            float4 hw = *(const float4*)(headw + tid * 4);
            sh[tid]       = b * hw.x;
            sh[tid + 128] = b * hw.y;
            sh[tid + 256] = b * hw.z;
            sh[tid + 384] = b * hw.w;
        }
        __syncthreads();
        int w = tid >> 5, lane = tid & 31;
        if (w < 4) {
            float s2 = sh[w * 128 + lane] + sh[w * 128 + lane + 32]
                     + sh[w * 128 + lane + 64] + sh[w * 128 + lane + 96];
#pragma unroll
            for (int off = 16; off; off >>= 1) s2 += __shfl_xor_sync(0xffffffffu, s2, off);
            if (lane == 0) g_bout[w] = headb[w] + s2;
        }
    }
}

// ---------------- main per-row-pair kernel -----------------------------------
template <int W>
__device__ __forceinline__ void attend_consume(
    const f2 (&G)[32], const f2 (&dwA)[2], const f2 (&dwO)[2],
    const f2 (&nbv)[2][7], const f2 (&obf)[2][2],
    const f2* __restrict__ wtab, const f2* __restrict__ bias, f2 (&ACC)[W])
{
    f2 lA[2][4], lO[2][4];
#pragma unroll
    for (int k = 0; k < 2; k++) {
#pragma unroll
        for (int h = 0; h < 4; h++) {
            f2 d = fmul2(nbv[k][0], G[h]);
#pragma unroll
            for (int j = 1; j < 6; j++) d = ffma2(nbv[k][j], G[j * 4 + h], d);
            lA[k][h] = fmul2(d, dwA[k]);
            f2 e = ffma2(obf[k][1], G[28 + h], fmul2(obf[k][0], G[24 + h]));
            lO[k][h] = fmul2(e, dwO[k]);
        }
    }
#pragma unroll
    for (int t = 0; t < W; t++) ACC[t] = bias[t];
#pragma unroll
    for (int h = 0; h < 4; h++) {
        {
            f2 e0 = expv(lA[0][h]), e1 = expv(lA[1][h]);
            f2 inv = rcpv(fadd2(e0, e1));
            f2 a0 = fmul2(e0, inv), a1 = fmul2(e1, inv);
#pragma unroll
            for (int j = 0; j < 7; j++) {
                f2 uv = ffma2(a1, nbv[1][j], fmul2(a0, nbv[0][j]));
                const f2* row = wtab + (j * 4 + h) * W;
#pragma unroll
                for (int t = 0; t < W; t += 2) {
                    ulonglong2 wp = *(const ulonglong2*)(row + t);
                    ACC[t]     = ffma2(uv, f2{wp.x}, ACC[t]);
                    ACC[t + 1] = ffma2(uv, f2{wp.y}, ACC[t + 1]);
                }
            }
        }
        {
            f2 e0 = expv(lO[0][h]), e1 = expv(lO[1][h]);
            f2 inv = rcpv(fadd2(e0, e1));
            f2 a0 = fmul2(e0, inv), a1 = fmul2(e1, inv);
#pragma unroll
            for (int j = 0; j < 2; j++) {
                f2 uv = ffma2(a1, obf[1][j], fmul2(a0, obf[0][j]));
                const f2* row = wtab + (28 + j * 4 + h) * W;
#pragma unroll
                for (int t = 0; t < W; t += 2) {
                    ulonglong2 wp = *(const ulonglong2*)(row + t);
                    ACC[t]     = ffma2(uv, f2{wp.x}, ACC[t]);
                    ACC[t + 1] = ffma2(uv, f2{wp.y}, ACC[t + 1]);
                }
            }
        }
    }
}

// dynamic smem layout
#define SM_OBS_F     (256 * 37)
#define SM_OBS_B     (SM_OBS_F * 4)
#define SM_WQK0_OFF  SM_OBS_B
#define SM_WG1_OFF   (SM_WQK0_OFF + 608 * 8)
#define SM_WOUT_OFF  (SM_WG1_OFF + 1152 * 8)
#define SM_BG1_OFF   (SM_WOUT_OFF + 144 * 8)
#define SM_BOUT_OFF  (SM_BG1_OFF + 32 * 8)
#define SM_TOTAL     (SM_BOUT_OFF + 4 * 8)

__global__ void __launch_bounds__(128)
actor_main(const float* __restrict__ obs,
           const float* __restrict__ ca0p, const float* __restrict__ co0p,
           const float* __restrict__ ca1p, const float* __restrict__ co1p,
           float* __restrict__ out, int n)
{
    extern __shared__ __align__(16) unsigned char smbuf[];
    float* sObs  = (float*)smbuf;
    f2* sWqk0 = (f2*)(smbuf + SM_WQK0_OFF);
    f2* sWG1  = (f2*)(smbuf + SM_WG1_OFF);
    f2* sWout = (f2*)(smbuf + SM_WOUT_OFF);
    f2* sbG1  = (f2*)(smbuf + SM_BG1_OFF);
    f2* sbout = (f2*)(smbuf + SM_BOUT_OFF);

    int tid = threadIdx.x;

    {
        long nel = (long)n * 37;
        long eb  = (long)blockIdx.x * 9472;
        const float4* g4 = (const float4*)obs;
        float4* s4 = (float4*)sObs;
#pragma unroll 4
        for (int i = tid; i < 2368; i += 128) {
            long e = eb + (long)i * 4;
            if (e + 3 < nel) {
                s4[i] = g4[eb / 4 + i];
            } else {
#pragma unroll
                for (int k = 0; k < 4; k++)
                    sObs[i * 4 + k] = (e + k < nel) ? obs[e + k] : 0.f;
            }
        }
    }
    for (int i = tid; i < 608;  i += 128) { float w = g_Wqk0[i]; sWqk0[i] = mkf2(w, w); }
    for (int i = tid; i < 1152; i += 128) { float w = g_WG1[i];  sWG1[i]  = mkf2(w, w); }
    for (int i = tid; i < 144;  i += 128) { float w = g_Wout[i]; sWout[i] = mkf2(w, w); }
    if (tid < 32) { float w = g_bG1[tid];  sbG1[tid]  = mkf2(w, w); }
    if (tid < 4)  { float w = g_bout[tid]; sbout[tid] = mkf2(w, w); }
    __syncthreads();

    int r0 = blockIdx.x * 256 + tid;
    if (r0 >= n) return;
    int r1 = r0 + 128;
    const float* lo = &sObs[tid * 37];
    const float* hi = &sObs[(tid + 128) * 37];

    float nca0 = -__ldg(ca0p), nco0 = -__ldg(co0p);
    float nca1 = -__ldg(ca1p), nco1 = -__ldg(co1p);

    f2 nbv[2][7], obf[2][2];
#pragma unroll
    for (int k = 0; k < 2; k++) {
#pragma unroll
        for (int j = 0; j < 6; j++) nbv[k][j] = mkf2(lo[12 + 6 * k + j], hi[12 + 6 * k + j]);
        nbv[k][6] = mkf2(lo[24 + k], hi[24 + k]);
        obf[k][0] = mkf2(lo[26 + 2 * k], hi[26 + 2 * k]);
        obf[k][1] = mkf2(lo[27 + 2 * k], hi[27 + 2 * k]);
    }

    float dAl[2], dAh[2], dOl[2], dOh[2];
    {
        float axl = lo[0], ayl = lo[1], axh = hi[0], ayh = hi[1];
#pragma unroll
        for (int k = 0; k < 2; k++) {
            float dx = axl - lo[12 + 6 * k], dy = ayl - lo[13 + 6 * k];
            dAl[k] = sqrtf(dx * dx + dy * dy);
            dx = axh - hi[12 + 6 * k]; dy = ayh - hi[13 + 6 * k];
            dAh[k] = sqrtf(dx * dx + dy * dy);
            dx = axl - lo[26 + 2 * k]; dy = ayl - lo[27 + 2 * k];
            dOl[k] = sqrtf(dx * dx + dy * dy);
            dx = axh - hi[26 + 2 * k]; dy = ayh - hi[27 + 2 * k];
            dOh[k] = sqrtf(dx * dx + dy * dy);
        }
    }
    f2 dwA0[2], dwO0[2], dwA1[2], dwO1[2];
#pragma unroll
    for (int k = 0; k < 2; k++) {
        dwA0[k] = mkf2(__expf(nca0 * dAl[k]), __expf(nca0 * dAh[k]));
        dwO0[k] = mkf2(__expf(nco0 * dOl[k]), __expf(nco0 * dOh[k]));
        dwA1[k] = mkf2(__expf(nca1 * dAl[k]), __expf(nca1 * dAh[k]));
        dwO1[k] = mkf2(__expf(nco1 * dOl[k]), __expf(nco1 * dOh[k]));
    }

    f2 G[32];
#pragma unroll
    for (int t = 0; t < 32; t++) G[t] = f2{0ull};
#pragma unroll
    for (int p = 0; p < 19; p++) {
        int src = (p < 12) ? p : p + 18;
        f2 q = mkf2(lo[src], hi[src]);
        const f2* row = sWqk0 + p * 32;
#pragma unroll
        for (int t = 0; t < 32; t += 2) {
            ulonglong2 wp = *(const ulonglong2*)(row + t);
            G[t]     = ffma2(q, f2{wp.x}, G[t]);
            G[t + 1] = ffma2(q, f2{wp.y}, G[t + 1]);
        }
    }

    f2 G1[32];
    attend_consume<32>(G, dwA0, dwO0, nbv, obf, sWG1, sbG1, G1);

    f2 R[4];
    attend_consume<4>(G1, dwA1, dwO1, nbv, obf, sWout, sbout, R);

    float o0l, o0h, o1l, o1h, o2l, o2h, o3l, o3h;
    unf2(R[0], o0l, o0h); unf2(R[1], o1l, o1h);
    unf2(R[2], o2l, o2h); unf2(R[3], o3l, o3h);
    ((float4*)out)[r0] = make_float4(o0l, o1l, o2l, o3l);
    if (r1 < n) ((float4*)out)[r1] = make_float4(o0h, o1h, o2h, o3h);
}

// ---------------- launch -----------------------------------------------------
extern "C" void kernel_launch(void* const* d_in, const int* in_sizes, int n_in,
                              void* d_out, int out_size)
{
    const float* obs   = (const float*)d_in[0];
    const float* wq0   = (const float*)d_in[1];
    const float* wak0  = (const float*)d_in[2];
    const float* wav0  = (const float*)d_in[3];
    const float* wok0  = (const float*)d_in[4];
    const float* wov0  = (const float*)d_in[5];
    const float* apw0  = (const float*)d_in[6];
    const float* apb0  = (const float*)d_in[7];
    const float* opw0  = (const float*)d_in[8];
    const float* opb0  = (const float*)d_in[9];
    const float* fpw0  = (const float*)d_in[10];
    const float* fpb0  = (const float*)d_in[11];
    const float* ca0   = (const float*)d_in[12];
    const float* co0   = (const float*)d_in[13];
    const float* wq1   = (const float*)d_in[14];
    const float* wak1  = (const float*)d_in[15];
    const float* wav1  = (const float*)d_in[16];
    const float* wok1  = (const float*)d_in[17];
    const float* wov1  = (const float*)d_in[18];
    const float* apw1  = (const float*)d_in[19];
    const float* apb1  = (const float*)d_in[20];
    const float* opw1  = (const float*)d_in[21];
    const float* opb1  = (const float*)d_in[22];
    const float* fpw1  = (const float*)d_in[23];
    const float* fpb1  = (const float*)d_in[24];
    const float* ca1   = (const float*)d_in[25];
    const float* co1   = (const float*)d_in[26];
    const float* headw = (const float*)d_in[27];
    const float* headb = (const float*)d_in[28];

    int n = in_sizes[0] / 37;

    pk1<<<221, 512>>>(wq0, wak0, wok0, wq1, wak1, wok1,
                      wav0, apw0, wov0, opw0, wav1, apw1, wov1, opw1,
                      fpb0, apb0, opb0, fpb1, apb1, opb1, fpw0, fpw1);
    pk2<<<74, 512>>>(fpw0, fpw1, headw, headb);

    cudaFuncSetAttribute(actor_main, cudaFuncAttributeMaxDynamicSharedMemorySize, SM_TOTAL);
    int grid = (n + 255) / 256;
    actor_main<<<grid, 128, SM_TOTAL>>>(obs, ca0, co0, ca1, co1, (float*)d_out, n);
}

// round 4
// speedup vs baseline: 1.5162x; 1.0258x over previous
#include <cuda_runtime.h>
#include <math.h>

// ---------------- folded-weight scratch (device globals) -------------------
__device__ float g_Wqk0[19 * 32];
__device__ float g_Wqk1[128 * 32];
__device__ float g_T0[36 * 128];
__device__ float g_T1[36 * 128];
__device__ float g_b0[128];
__device__ float g_b1[128];
__device__ float g_WG1[36 * 32];
__device__ float g_bG1[32];
__device__ float g_Wout[36 * 4];
__device__ float g_bout[4];

#define QK_SCALE 0.17677669529663687f   // 1/sqrt(32)

// ---------------- packed f32x2 helpers --------------------------------------
struct f2 { unsigned long long v; };

__device__ __forceinline__ f2 mkf2(float lo, float hi) {
    f2 r; asm("mov.b64 %0,{%1,%2};" : "=l"(r.v) : "f"(lo), "f"(hi)); return r;
}
__device__ __forceinline__ void unf2(f2 a, float& lo, float& hi) {
    asm("mov.b64 {%0,%1},%2;" : "=f"(lo), "=f"(hi) : "l"(a.v));
}
__device__ __forceinline__ f2 ffma2(f2 a, f2 b, f2 c) {
    f2 r; asm("fma.rn.f32x2 %0,%1,%2,%3;" : "=l"(r.v) : "l"(a.v), "l"(b.v), "l"(c.v)); return r;
}
__device__ __forceinline__ f2 fmul2(f2 a, f2 b) {
    f2 r; asm("mul.rn.f32x2 %0,%1,%2;" : "=l"(r.v) : "l"(a.v), "l"(b.v)); return r;
}
__device__ __forceinline__ float sigf(float d) {   // 1/(1+exp(-d))
    float e = __expf(-d);
    float r;
    asm("rcp.approx.f32 %0,%1;" : "=f"(r) : "f"(1.f + e));
    return r;
}

// ---------------- precompute kernel 1 ----------------------------------------
// All independent global loads issued BEFORE the first sync -> one DRAM round.
__global__ void __launch_bounds__(512, 2)
pk1(const float* __restrict__ wq0, const float* __restrict__ wak0,
    const float* __restrict__ wok0,
    const float* __restrict__ wq1, const float* __restrict__ wak1,
    const float* __restrict__ wok1,
    const float* __restrict__ wav0, const float* __restrict__ apw0,
    const float* __restrict__ wov0, const float* __restrict__ opw0,
    const float* __restrict__ wav1, const float* __restrict__ apw1,
    const float* __restrict__ wov1, const float* __restrict__ opw1,
    const float* __restrict__ fpb0, const float* __restrict__ apb0,
    const float* __restrict__ opb0,
    const float* __restrict__ fpb1, const float* __restrict__ apb1,
    const float* __restrict__ opb1,
    const float* __restrict__ fpw0, const float* __restrict__ fpw1)
{
    __shared__ float sh[512];
    __shared__ float svec[128];
    int bid = blockIdx.x, tid = threadIdx.x;

    if (bid < 72) {
        int L = bid / 36, t = bid % 36, h = t & 3;
        const float* wv; const float* pw; int j;
        if (L == 0) {
            if (t < 28) { wv = wav0; pw = apw0; j = t >> 2; }
            else        { wv = wov0; pw = opw0; j = (t - 28) >> 2; }
        } else {
            if (t < 28) { wv = wav1; pw = apw1; j = t >> 2; }
            else        { wv = wov1; pw = opw1; j = (t - 28) >> 2; }
        }
        int q = tid >> 7, m = tid & 127;
        const float* base = pw + h * 16384 + q * 4096 + m;
        float pwv[32];
#pragma unroll
        for (int i = 0; i < 32; i++) pwv[i] = __ldg(base + i * 128);
        if (tid < 128) svec[tid] = wv[j * 512 + h * 128 + tid];
        __syncthreads();
        float s = 0.f;
#pragma unroll
        for (int i = 0; i < 32; i++) s += svec[q * 32 + i] * pwv[i];
        sh[tid] = s;
        __syncthreads();
        if (tid < 128)
            (L ? g_T1 : g_T0)[t * 128 + tid] =
                (sh[tid] + sh[tid + 128]) + (sh[tid + 256] + sh[tid + 384]);
    } else if (bid < 219) {
        int r = bid - 72;
        const float* wq; const float* wak; const float* wok; float* dst; int rowoff;
        if (r < 19) { wq = wq0; wak = wak0; wok = wok0; dst = g_Wqk0 + r * 32; rowoff = r * 512; }
        else { r -= 19; wq = wq1; wak = wak1; wok = wok1; dst = g_Wqk1 + r * 32; rowoff = r * 512; }
        int t = tid >> 4, ci = tid & 15, h = t & 3;
        const float* wk; int j;
        if (t < 24) { wk = wak; j = t >> 2; } else { wk = wok; j = (t - 24) >> 2; }
        const float4* a4 = (const float4*)(wq + rowoff + h * 128 + ci * 8);
        const float4* b4 = (const float4*)(wk + j * 512 + h * 128 + ci * 8);
        float4 a0 = a4[0], a1 = a4[1], b0 = b4[0], b1 = b4[1];
        float s = a0.x * b0.x + a0.y * b0.y + a0.z * b0.z + a0.w * b0.w
                + a1.x * b1.x + a1.y * b1.y + a1.z * b1.z + a1.w * b1.w;
#pragma unroll
        for (int off = 8; off; off >>= 1) s += __shfl_xor_sync(0xffffffffu, s, off);
        if (ci == 0) dst[t] = s * QK_SCALE;
    } else {
        const float* fpb; const float* apb; const float* opb; const float* fpw; float* gb;
        if (bid == 219) { fpb = fpb0; apb = apb0; opb = opb0; fpw = fpw0; gb = g_b0; }
        else            { fpb = fpb1; apb = apb1; opb = opb1; fpw = fpw1; gb = g_b1; }
        int q = tid >> 7, m = tid & 127;
        float s = 0.f;
#pragma unroll
        for (int i = 0; i < 32; i++) {
            int m1 = q * 32 + i;
            s += apb[m1] * fpw[m1 * 128 + m] + opb[m1] * fpw[(128 + m1) * 128 + m];
        }
        sh[tid] = s;
        __syncthreads();
        if (tid < 128)
            gb[tid] = fpb[tid] + (sh[tid] + sh[tid + 128]) + (sh[tid + 256] + sh[tid + 384]);
    }
}

// ---------------- precompute kernel 2 ----------------------------------------
// Stage-B operands (g_Wqk1 / headw) prefetched before stage-A sync.
__global__ void __launch_bounds__(512, 2)
pk2(const float* __restrict__ fpw0, const float* __restrict__ fpw1,
    const float* __restrict__ headw, const float* __restrict__ headb)
{
    __shared__ float sh[512];
    __shared__ float sT[128], sW[128];
    int bid = blockIdx.x, tid = threadIdx.x;

    if (bid < 72) {
        int which = bid / 36, t = bid % 36;
        const float* gT  = which ? g_T1 : g_T0;
        const float* fpw = which ? fpw1 : fpw0;
        int q = tid >> 7, m = tid & 127;
        int t2 = tid >> 4, mi = tid & 15;

        // --- prefetch stage-B operands (independent of stage A) ---
        float wreg[8];
        float4 hw = make_float4(0.f, 0.f, 0.f, 0.f);
        if (which == 0) {
#pragma unroll
            for (int i = 0; i < 8; i++) wreg[i] = g_Wqk1[(mi * 8 + i) * 32 + t2];
        } else if (tid < 128) {
            hw = *(const float4*)(headw + tid * 4);
        }
        // --- stage-A loads ---
        float fv[32];
        const float* base = fpw + (t < 28 ? 0 : 16384) + q * 4096 + m;
#pragma unroll
        for (int i = 0; i < 32; i++) fv[i] = __ldg(base + i * 128);
        if (tid < 128) sT[tid] = gT[t * 128 + tid];
        __syncthreads();
        float s = 0.f;
#pragma unroll
        for (int i = 0; i < 32; i++) s += sT[q * 32 + i] * fv[i];
        sh[tid] = s;
        __syncthreads();
        if (tid < 128)
            sW[tid] = (sh[tid] + sh[tid + 128]) + (sh[tid + 256] + sh[tid + 384]);
        __syncthreads();
        if (which == 0) {
            float s2 = 0.f;
#pragma unroll
            for (int i = 0; i < 8; i++) s2 += sW[mi * 8 + i] * wreg[i];
#pragma unroll
            for (int off = 8; off; off >>= 1) s2 += __shfl_xor_sync(0xffffffffu, s2, off);
            if (mi == 0) g_WG1[t * 32 + t2] = s2;
        } else {
            if (tid < 128) {
                float w0 = sW[tid];
                sh[tid]       = w0 * hw.x;
                sh[tid + 128] = w0 * hw.y;
                sh[tid + 256] = w0 * hw.z;
                sh[tid + 384] = w0 * hw.w;
            }
            __syncthreads();
            int w = tid >> 5, lane = tid & 31;
            if (w < 4) {
                float s2 = sh[w * 128 + lane] + sh[w * 128 + lane + 32]
                         + sh[w * 128 + lane + 64] + sh[w * 128 + lane + 96];
#pragma unroll
                for (int off = 16; off; off >>= 1) s2 += __shfl_xor_sync(0xffffffffu, s2, off);
                if (lane == 0) g_Wout[t * 4 + w] = s2;
            }
        }
    } else if (bid == 72) {
        int t2 = tid & 31, mq = tid >> 5;
        float b8[8], w8[8];
#pragma unroll
        for (int i = 0; i < 8; i++) {
            int m = mq * 8 + i;
            b8[i] = g_b0[m];
            w8[i] = g_Wqk1[m * 32 + t2];
        }
        float s = 0.f;
#pragma unroll
        for (int i = 0; i < 8; i++) s += b8[i] * w8[i];
        sh[tid] = s;
        __syncthreads();
        if (tid < 32) {
            float s2 = 0.f;
#pragma unroll
            for (int g = 0; g < 16; g++) s2 += sh[g * 32 + tid];
            g_bG1[tid] = s2;
        }
    } else {
        if (tid < 128) {
            float b = g_b1[tid];
            float4 hw = *(const float4*)(headw + tid * 4);
            sh[tid]       = b * hw.x;
            sh[tid + 128] = b * hw.y;
            sh[tid + 256] = b * hw.z;
            sh[tid + 384] = b * hw.w;
        }
        __syncthreads();
        int w = tid >> 5, lane = tid & 31;
        if (w < 4) {
            float s2 = sh[w * 128 + lane] + sh[w * 128 + lane + 32]
                     + sh[w * 128 + lane + 64] + sh[w * 128 + lane + 96];
#pragma unroll
            for (int off = 16; off; off >>= 1) s2 += __shfl_xor_sync(0xffffffffu, s2, off);
            if (lane == 0) g_bout[w] = headb[w] + s2;
        }
    }
}

// ---------------- main per-row-pair kernel -----------------------------------
// Sigmoid form of the K=2 softmax: a0 = sigma(l0-l1), u = v1 + a0*(v0-v1).
template <int W>
__device__ __forceinline__ void attend_consume(
    const f2 (&G)[32], const f2 (&dwA)[2], const f2 (&dwO)[2],
    const f2 (&nbv)[2][7], const f2 (&dnbv)[7],
    const f2 (&obf)[2][2], const f2 (&dobf)[2],
    const f2* __restrict__ wtab, const f2* __restrict__ bias, f2 (&ACC)[W])
{
    f2 lA[2][4], lO[2][4];
#pragma unroll
    for (int k = 0; k < 2; k++) {
#pragma unroll
        for (int h = 0; h < 4; h++) {
            f2 d = fmul2(nbv[k][0], G[h]);
#pragma unroll
            for (int j = 1; j < 6; j++) d = ffma2(nbv[k][j], G[j * 4 + h], d);
            lA[k][h] = fmul2(d, dwA[k]);
            f2 e = ffma2(obf[k][1], G[28 + h], fmul2(obf[k][0], G[24 + h]));
            lO[k][h] = fmul2(e, dwO[k]);
        }
    }
#pragma unroll
    for (int t = 0; t < W; t++) ACC[t] = bias[t];
#pragma unroll
    for (int h = 0; h < 4; h++) {
        {
            float l0l, l0h, l1l, l1h;
            unf2(lA[0][h], l0l, l0h); unf2(lA[1][h], l1l, l1h);
            f2 a0 = mkf2(sigf(l0l - l1l), sigf(l0h - l1h));
#pragma unroll
            for (int j = 0; j < 7; j++) {
                f2 uv = ffma2(a0, dnbv[j], nbv[1][j]);
                const f2* row = wtab + (j * 4 + h) * W;
#pragma unroll
                for (int t = 0; t < W; t += 2) {
                    ulonglong2 wp = *(const ulonglong2*)(row + t);
                    ACC[t]     = ffma2(uv, f2{wp.x}, ACC[t]);
                    ACC[t + 1] = ffma2(uv, f2{wp.y}, ACC[t + 1]);
                }
            }
        }
        {
            float l0l, l0h, l1l, l1h;
            unf2(lO[0][h], l0l, l0h); unf2(lO[1][h], l1l, l1h);
            f2 a0 = mkf2(sigf(l0l - l1l), sigf(l0h - l1h));
#pragma unroll
            for (int j = 0; j < 2; j++) {
                f2 uv = ffma2(a0, dobf[j], obf[1][j]);
                const f2* row = wtab + (28 + j * 4 + h) * W;
#pragma unroll
                for (int t = 0; t < W; t += 2) {
                    ulonglong2 wp = *(const ulonglong2*)(row + t);
                    ACC[t]     = ffma2(uv, f2{wp.x}, ACC[t]);
                    ACC[t + 1] = ffma2(uv, f2{wp.y}, ACC[t + 1]);
                }
            }
        }
    }
}

// dynamic smem layout
#define SM_OBS_F     (256 * 37)
#define SM_OBS_B     (SM_OBS_F * 4)
#define SM_WQK0_OFF  SM_OBS_B
#define SM_WG1_OFF   (SM_WQK0_OFF + 608 * 8)
#define SM_WOUT_OFF  (SM_WG1_OFF + 1152 * 8)
#define SM_BG1_OFF   (SM_WOUT_OFF + 144 * 8)
#define SM_BOUT_OFF  (SM_BG1_OFF + 32 * 8)
#define SM_TOTAL     (SM_BOUT_OFF + 4 * 8)

__global__ void __launch_bounds__(128)
actor_main(const float* __restrict__ obs,
           const float* __restrict__ ca0p, const float* __restrict__ co0p,
           const float* __restrict__ ca1p, const float* __restrict__ co1p,
           float* __restrict__ out, int n)
{
    extern __shared__ __align__(16) unsigned char smbuf[];
    float* sObs  = (float*)smbuf;
    f2* sWqk0 = (f2*)(smbuf + SM_WQK0_OFF);
    f2* sWG1  = (f2*)(smbuf + SM_WG1_OFF);
    f2* sWout = (f2*)(smbuf + SM_WOUT_OFF);
    f2* sbG1  = (f2*)(smbuf + SM_BG1_OFF);
    f2* sbout = (f2*)(smbuf + SM_BOUT_OFF);

    int tid = threadIdx.x;

    {
        long nel = (long)n * 37;
        long eb  = (long)blockIdx.x * 9472;
        const float4* g4 = (const float4*)obs;
        float4* s4 = (float4*)sObs;
#pragma unroll 4
        for (int i = tid; i < 2368; i += 128) {
            long e = eb + (long)i * 4;
            if (e + 3 < nel) {
                s4[i] = g4[eb / 4 + i];
            } else {
#pragma unroll
                for (int k = 0; k < 4; k++)
                    sObs[i * 4 + k] = (e + k < nel) ? obs[e + k] : 0.f;
            }
        }
    }
    for (int i = tid; i < 608;  i += 128) { float w = g_Wqk0[i]; sWqk0[i] = mkf2(w, w); }
    for (int i = tid; i < 1152; i += 128) { float w = g_WG1[i];  sWG1[i]  = mkf2(w, w); }
    for (int i = tid; i < 144;  i += 128) { float w = g_Wout[i]; sWout[i] = mkf2(w, w); }
    if (tid < 32) { float w = g_bG1[tid];  sbG1[tid]  = mkf2(w, w); }
    if (tid < 4)  { float w = g_bout[tid]; sbout[tid] = mkf2(w, w); }
    __syncthreads();

    int r0 = blockIdx.x * 256 + tid;
    if (r0 >= n) return;
    int r1 = r0 + 128;
    const float* lo = &sObs[tid * 37];
    const float* hi = &sObs[(tid + 128) * 37];

    float nca0 = -__ldg(ca0p), nco0 = -__ldg(co0p);
    float nca1 = -__ldg(ca1p), nco1 = -__ldg(co1p);

    f2 nbv[2][7], obf[2][2], dnbv[7], dobf[2];
    f2 negone = mkf2(-1.f, -1.f);
#pragma unroll
    for (int k = 0; k < 2; k++) {
#pragma unroll
        for (int j = 0; j < 6; j++) nbv[k][j] = mkf2(lo[12 + 6 * k + j], hi[12 + 6 * k + j]);
        nbv[k][6] = mkf2(lo[24 + k], hi[24 + k]);
        obf[k][0] = mkf2(lo[26 + 2 * k], hi[26 + 2 * k]);
        obf[k][1] = mkf2(lo[27 + 2 * k], hi[27 + 2 * k]);
    }
#pragma unroll
    for (int j = 0; j < 7; j++) dnbv[j] = ffma2(nbv[1][j], negone, nbv[0][j]);
#pragma unroll
    for (int j = 0; j < 2; j++) dobf[j] = ffma2(obf[1][j], negone, obf[0][j]);

    float dAl[2], dAh[2], dOl[2], dOh[2];
    {
        float axl = lo[0], ayl = lo[1], axh = hi[0], ayh = hi[1];
#pragma unroll
        for (int k = 0; k < 2; k++) {
            float dx = axl - lo[12 + 6 * k], dy = ayl - lo[13 + 6 * k];
            dAl[k] = sqrtf(dx * dx + dy * dy);
            dx = axh - hi[12 + 6 * k]; dy = ayh - hi[13 + 6 * k];
            dAh[k] = sqrtf(dx * dx + dy * dy);
            dx = axl - lo[26 + 2 * k]; dy = ayl - lo[27 + 2 * k];
            dOl[k] = sqrtf(dx * dx + dy * dy);
            dx = axh - hi[26 + 2 * k]; dy = ayh - hi[27 + 2 * k];
            dOh[k] = sqrtf(dx * dx + dy * dy);
        }
    }
    f2 dwA0[2], dwO0[2], dwA1[2], dwO1[2];
#pragma unroll
    for (int k = 0; k < 2; k++) {
        dwA0[k] = mkf2(__expf(nca0 * dAl[k]), __expf(nca0 * dAh[k]));
        dwO0[k] = mkf2(__expf(nco0 * dOl[k]), __expf(nco0 * dOh[k]));
        dwA1[k] = mkf2(__expf(nca1 * dAl[k]), __expf(nca1 * dAh[k]));
        dwO1[k] = mkf2(__expf(nco1 * dOl[k]), __expf(nco1 * dOh[k]));
    }

    f2 G[32];
#pragma unroll
    for (int t = 0; t < 32; t++) G[t] = f2{0ull};
#pragma unroll
    for (int p = 0; p < 19; p++) {
        int src = (p < 12) ? p : p + 18;
        f2 q = mkf2(lo[src], hi[src]);
        const f2* row = sWqk0 + p * 32;
#pragma unroll
        for (int t = 0; t < 32; t += 2) {
            ulonglong2 wp = *(const ulonglong2*)(row + t);
            G[t]     = ffma2(q, f2{wp.x}, G[t]);
            G[t + 1] = ffma2(q, f2{wp.y}, G[t + 1]);
        }
    }

    f2 G1[32];
    attend_consume<32>(G, dwA0, dwO0, nbv, dnbv, obf, dobf, sWG1, sbG1, G1);

    f2 R[4];
    attend_consume<4>(G1, dwA1, dwO1, nbv, dnbv, obf, dobf, sWout, sbout, R);

    float o0l, o0h, o1l, o1h, o2l, o2h, o3l, o3h;
    unf2(R[0], o0l, o0h); unf2(R[1], o1l, o1h);
    unf2(R[2], o2l, o2h); unf2(R[3], o3l, o3h);
    ((float4*)out)[r0] = make_float4(o0l, o1l, o2l, o3l);
    if (r1 < n) ((float4*)out)[r1] = make_float4(o0h, o1h, o2h, o3h);
}

// ---------------- launch -----------------------------------------------------
extern "C" void kernel_launch(void* const* d_in, const int* in_sizes, int n_in,
                              void* d_out, int out_size)
{
    const float* obs   = (const float*)d_in[0];
    const float* wq0   = (const float*)d_in[1];
    const float* wak0  = (const float*)d_in[2];
    const float* wav0  = (const float*)d_in[3];
    const float* wok0  = (const float*)d_in[4];
    const float* wov0  = (const float*)d_in[5];
    const float* apw0  = (const float*)d_in[6];
    const float* apb0  = (const float*)d_in[7];
    const float* opw0  = (const float*)d_in[8];
    const float* opb0  = (const float*)d_in[9];
    const float* fpw0  = (const float*)d_in[10];
    const float* fpb0  = (const float*)d_in[11];
    const float* ca0   = (const float*)d_in[12];
    const float* co0   = (const float*)d_in[13];
    const float* wq1   = (const float*)d_in[14];
    const float* wak1  = (const float*)d_in[15];
    const float* wav1  = (const float*)d_in[16];
    const float* wok1  = (const float*)d_in[17];
    const float* wov1  = (const float*)d_in[18];
    const float* apw1  = (const float*)d_in[19];
    const float* apb1  = (const float*)d_in[20];
    const float* opw1  = (const float*)d_in[21];
    const float* opb1  = (const float*)d_in[22];
    const float* fpw1  = (const float*)d_in[23];
    const float* fpb1  = (const float*)d_in[24];
    const float* ca1   = (const float*)d_in[25];
    const float* co1   = (const float*)d_in[26];
    const float* headw = (const float*)d_in[27];
    const float* headb = (const float*)d_in[28];

    int n = in_sizes[0] / 37;

    pk1<<<221, 512>>>(wq0, wak0, wok0, wq1, wak1, wok1,
                      wav0, apw0, wov0, opw0, wav1, apw1, wov1, opw1,
                      fpb0, apb0, opb0, fpb1, apb1, opb1, fpw0, fpw1);
    pk2<<<74, 512>>>(fpw0, fpw1, headw, headb);

    cudaFuncSetAttribute(actor_main, cudaFuncAttributeMaxDynamicSharedMemorySize, SM_TOTAL);
    int grid = (n + 255) / 256;
    actor_main<<<grid, 128, SM_TOTAL>>>(obs, ca0, co0, ca1, co1, (float*)d_out, n);
}

// round 5
// speedup vs baseline: 1.5853x; 1.0456x over previous
#include <cuda_runtime.h>
#include <math.h>

// ---------------- folded-weight scratch (device globals) -------------------
__device__ float g_Wqk0[19 * 32];
__device__ float g_Wqk1[128 * 32];
__device__ float g_b0[128];
__device__ float g_b1[128];
__device__ float g_WG1[36 * 32];
__device__ float g_bG1[32];
__device__ float g_Wout[36 * 4];
__device__ float g_bout[4];

#define QK_SCALE 0.17677669529663687f   // 1/sqrt(32)

// ---------------- packed f32x2 helpers --------------------------------------
struct f2 { unsigned long long v; };

__device__ __forceinline__ f2 mkf2(float lo, float hi) {
    f2 r; asm("mov.b64 %0,{%1,%2};" : "=l"(r.v) : "f"(lo), "f"(hi)); return r;
}
__device__ __forceinline__ void unf2(f2 a, float& lo, float& hi) {
    asm("mov.b64 {%0,%1},%2;" : "=f"(lo), "=f"(hi) : "l"(a.v));
}
__device__ __forceinline__ f2 ffma2(f2 a, f2 b, f2 c) {
    f2 r; asm("fma.rn.f32x2 %0,%1,%2,%3;" : "=l"(r.v) : "l"(a.v), "l"(b.v), "l"(c.v)); return r;
}
__device__ __forceinline__ f2 fmul2(f2 a, f2 b) {
    f2 r; asm("mul.rn.f32x2 %0,%1,%2;" : "=l"(r.v) : "l"(a.v), "l"(b.v)); return r;
}
__device__ __forceinline__ float sigf(float d) {   // 1/(1+exp(-d))
    float e = __expf(-d);
    float r;
    asm("rcp.approx.f32 %0,%1;" : "=f"(r) : "f"(1.f + e));
    return r;
}

// ---------------- precompute kernel 1 ----------------------------------------
// bid [0,19):    Wqk0 rows
// bid [19,147):  Wqk1 rows
// bid 147/148:   b0/b1
__global__ void __launch_bounds__(512, 1)
pk1(const float* __restrict__ wq0, const float* __restrict__ wak0,
    const float* __restrict__ wok0,
    const float* __restrict__ wq1, const float* __restrict__ wak1,
    const float* __restrict__ wok1,
    const float* __restrict__ fpb0, const float* __restrict__ apb0,
    const float* __restrict__ opb0,
    const float* __restrict__ fpb1, const float* __restrict__ apb1,
    const float* __restrict__ opb1,
    const float* __restrict__ fpw0, const float* __restrict__ fpw1)
{
    __shared__ float sh[512];
    int bid = blockIdx.x, tid = threadIdx.x;

    if (bid < 147) {
        const float* wq; const float* wak; const float* wok; float* dst; int rowoff;
        if (bid < 19) { wq = wq0; wak = wak0; wok = wok0; dst = g_Wqk0 + bid * 32; rowoff = bid * 512; }
        else { int r = bid - 19; wq = wq1; wak = wak1; wok = wok1; dst = g_Wqk1 + r * 32; rowoff = r * 512; }
        int t = tid >> 4, ci = tid & 15, h = t & 3;
        const float* wk; int j;
        if (t < 24) { wk = wak; j = t >> 2; } else { wk = wok; j = (t - 24) >> 2; }
        const float4* a4 = (const float4*)(wq + rowoff + h * 128 + ci * 8);
        const float4* b4 = (const float4*)(wk + j * 512 + h * 128 + ci * 8);
        float4 a0 = a4[0], a1 = a4[1], b0 = b4[0], b1 = b4[1];
        float s = a0.x * b0.x + a0.y * b0.y + a0.z * b0.z + a0.w * b0.w
                + a1.x * b1.x + a1.y * b1.y + a1.z * b1.z + a1.w * b1.w;
#pragma unroll
        for (int off = 8; off; off >>= 1) s += __shfl_xor_sync(0xffffffffu, s, off);
        if (ci == 0) dst[t] = s * QK_SCALE;
    } else {
        const float* fpb; const float* apb; const float* opb; const float* fpw; float* gb;
        if (bid == 147) { fpb = fpb0; apb = apb0; opb = opb0; fpw = fpw0; gb = g_b0; }
        else            { fpb = fpb1; apb = apb1; opb = opb1; fpw = fpw1; gb = g_b1; }
        int q = tid >> 7, m = tid & 127;
        // full prefetch: both fpw panels + bias values
        float fa[32], fo[32];
        const float* basea = fpw + q * 4096 + m;
        const float* baseo = fpw + 16384 + q * 4096 + m;
#pragma unroll
        for (int i = 0; i < 32; i++) fa[i] = __ldg(basea + i * 128);
#pragma unroll
        for (int i = 0; i < 32; i++) fo[i] = __ldg(baseo + i * 128);
        float s = 0.f;
#pragma unroll
        for (int i = 0; i < 32; i++) {
            int m1 = q * 32 + i;
            s += apb[m1] * fa[i] + opb[m1] * fo[i];
        }
        sh[tid] = s;
        __syncthreads();
        if (tid < 128)
            gb[tid] = fpb[tid] + (sh[tid] + sh[tid + 128]) + (sh[tid + 256] + sh[tid + 384]);
    }
}

// ---------------- precompute kernel 2 ----------------------------------------
// bid [0,72): (which,t): computes T row, W row, and WG1/Wout row, with ALL
//             global loads for all three stages issued before the first sync.
// bid 72: bG1, bid 73: bout
__global__ void __launch_bounds__(512, 1)
pk2(const float* __restrict__ wav0, const float* __restrict__ apw0,
    const float* __restrict__ wov0, const float* __restrict__ opw0,
    const float* __restrict__ wav1, const float* __restrict__ apw1,
    const float* __restrict__ wov1, const float* __restrict__ opw1,
    const float* __restrict__ fpw0, const float* __restrict__ fpw1,
    const float* __restrict__ headw, const float* __restrict__ headb)
{
    __shared__ float sh[512];
    __shared__ float svec[128], sT[128], sW[128];
    int bid = blockIdx.x, tid = threadIdx.x;

    if (bid < 72) {
        int which = bid / 36, t = bid % 36, h = t & 3;
        const float* wv; const float* pw; int j;
        if (which == 0) {
            if (t < 28) { wv = wav0; pw = apw0; j = t >> 2; }
            else        { wv = wov0; pw = opw0; j = (t - 28) >> 2; }
        } else {
            if (t < 28) { wv = wav1; pw = apw1; j = t >> 2; }
            else        { wv = wov1; pw = opw1; j = (t - 28) >> 2; }
        }
        const float* fpw = which ? fpw1 : fpw0;
        int q = tid >> 7, m = tid & 127;
        int t2 = tid >> 4, mi = tid & 15;

        // ---- prefetch everything (one DRAM round) ----
        float pwv[32], fv[32];
        const float* baseT = pw + h * 16384 + q * 4096 + m;
        const float* baseW = fpw + (t < 28 ? 0 : 16384) + q * 4096 + m;
#pragma unroll
        for (int i = 0; i < 32; i++) pwv[i] = __ldg(baseT + i * 128);
#pragma unroll
        for (int i = 0; i < 32; i++) fv[i] = __ldg(baseW + i * 128);
        float wreg[8];
        float4 hw = make_float4(0.f, 0.f, 0.f, 0.f);
        if (which == 0) {
#pragma unroll
            for (int i = 0; i < 8; i++) wreg[i] = g_Wqk1[(mi * 8 + i) * 32 + t2];
        } else if (tid < 128) {
            hw = *(const float4*)(headw + tid * 4);
        }
        if (tid < 128) svec[tid] = wv[j * 512 + h * 128 + tid];
        __syncthreads();

        // ---- stage T ----
        float s = 0.f;
#pragma unroll
        for (int i = 0; i < 32; i++) s += svec[q * 32 + i] * pwv[i];
        sh[tid] = s;
        __syncthreads();
        if (tid < 128)
            sT[tid] = (sh[tid] + sh[tid + 128]) + (sh[tid + 256] + sh[tid + 384]);
        __syncthreads();

        // ---- stage W ----
        s = 0.f;
#pragma unroll
        for (int i = 0; i < 32; i++) s += sT[q * 32 + i] * fv[i];
        sh[tid] = s;
        __syncthreads();
        if (tid < 128)
            sW[tid] = (sh[tid] + sh[tid + 128]) + (sh[tid + 256] + sh[tid + 384]);
        __syncthreads();

        // ---- stage B ----
        if (which == 0) {
            float s2 = 0.f;
#pragma unroll
            for (int i = 0; i < 8; i++) s2 += sW[mi * 8 + i] * wreg[i];
#pragma unroll
            for (int off = 8; off; off >>= 1) s2 += __shfl_xor_sync(0xffffffffu, s2, off);
            if (mi == 0) g_WG1[t * 32 + t2] = s2;
        } else {
            if (tid < 128) {
                float w0 = sW[tid];
                sh[tid]       = w0 * hw.x;
                sh[tid + 128] = w0 * hw.y;
                sh[tid + 256] = w0 * hw.z;
                sh[tid + 384] = w0 * hw.w;
            }
            __syncthreads();
            int w = tid >> 5, lane = tid & 31;
            if (w < 4) {
                float s2 = sh[w * 128 + lane] + sh[w * 128 + lane + 32]
                         + sh[w * 128 + lane + 64] + sh[w * 128 + lane + 96];
#pragma unroll
                for (int off = 16; off; off >>= 1) s2 += __shfl_xor_sync(0xffffffffu, s2, off);
                if (lane == 0) g_Wout[t * 4 + w] = s2;
            }
        }
    } else if (bid == 72) {
        int t2 = tid & 31, mq = tid >> 5;
        float b8[8], w8[8];
#pragma unroll
        for (int i = 0; i < 8; i++) {
            int m = mq * 8 + i;
            b8[i] = g_b0[m];
            w8[i] = g_Wqk1[m * 32 + t2];
        }
        float s = 0.f;
#pragma unroll
        for (int i = 0; i < 8; i++) s += b8[i] * w8[i];
        sh[tid] = s;
        __syncthreads();
        if (tid < 32) {
            float s2 = 0.f;
#pragma unroll
            for (int g = 0; g < 16; g++) s2 += sh[g * 32 + tid];
            g_bG1[tid] = s2;
        }
    } else {
        if (tid < 128) {
            float b = g_b1[tid];
            float4 hw = *(const float4*)(headw + tid * 4);
            sh[tid]       = b * hw.x;
            sh[tid + 128] = b * hw.y;
            sh[tid + 256] = b * hw.z;
            sh[tid + 384] = b * hw.w;
        }
        __syncthreads();
        int w = tid >> 5, lane = tid & 31;
        if (w < 4) {
            float s2 = sh[w * 128 + lane] + sh[w * 128 + lane + 32]
                     + sh[w * 128 + lane + 64] + sh[w * 128 + lane + 96];
#pragma unroll
            for (int off = 16; off; off >>= 1) s2 += __shfl_xor_sync(0xffffffffu, s2, off);
            if (lane == 0) g_bout[w] = headb[w] + s2;
        }
    }
}

// ---------------- main per-row-pair kernel -----------------------------------
template <int W>
__device__ __forceinline__ void attend_consume(
    const f2 (&G)[32], const f2 (&dwA)[2], const f2 (&dwO)[2],
    const f2 (&nbv)[2][7], const f2 (&dnbv)[7],
    const f2 (&obf)[2][2], const f2 (&dobf)[2],
    const f2* __restrict__ wtab, const f2* __restrict__ bias, f2 (&ACC)[W])
{
    f2 lA[2][4], lO[2][4];
#pragma unroll
    for (int k = 0; k < 2; k++) {
#pragma unroll
        for (int h = 0; h < 4; h++) {
            f2 d = fmul2(nbv[k][0], G[h]);
#pragma unroll
            for (int j = 1; j < 6; j++) d = ffma2(nbv[k][j], G[j * 4 + h], d);
            lA[k][h] = fmul2(d, dwA[k]);
            f2 e = ffma2(obf[k][1], G[28 + h], fmul2(obf[k][0], G[24 + h]));
            lO[k][h] = fmul2(e, dwO[k]);
        }
    }
#pragma unroll
    for (int t = 0; t < W; t++) ACC[t] = bias[t];
#pragma unroll
    for (int h = 0; h < 4; h++) {
        {
            float l0l, l0h, l1l, l1h;
            unf2(lA[0][h], l0l, l0h); unf2(lA[1][h], l1l, l1h);
            f2 a0 = mkf2(sigf(l0l - l1l), sigf(l0h - l1h));
#pragma unroll
            for (int j = 0; j < 7; j++) {
                f2 uv = ffma2(a0, dnbv[j], nbv[1][j]);
                const f2* row = wtab + (j * 4 + h) * W;
#pragma unroll
                for (int t = 0; t < W; t += 2) {
                    ulonglong2 wp = *(const ulonglong2*)(row + t);
                    ACC[t]     = ffma2(uv, f2{wp.x}, ACC[t]);
                    ACC[t + 1] = ffma2(uv, f2{wp.y}, ACC[t + 1]);
                }
            }
        }
        {
            float l0l, l0h, l1l, l1h;
            unf2(lO[0][h], l0l, l0h); unf2(lO[1][h], l1l, l1h);
            f2 a0 = mkf2(sigf(l0l - l1l), sigf(l0h - l1h));
#pragma unroll
            for (int j = 0; j < 2; j++) {
                f2 uv = ffma2(a0, dobf[j], obf[1][j]);
                const f2* row = wtab + (28 + j * 4 + h) * W;
#pragma unroll
                for (int t = 0; t < W; t += 2) {
                    ulonglong2 wp = *(const ulonglong2*)(row + t);
                    ACC[t]     = ffma2(uv, f2{wp.x}, ACC[t]);
                    ACC[t + 1] = ffma2(uv, f2{wp.y}, ACC[t + 1]);
                }
            }
        }
    }
}

// dynamic smem layout
#define SM_OBS_F     (256 * 37)
#define SM_OBS_B     (SM_OBS_F * 4)
#define SM_WQK0_OFF  SM_OBS_B
#define SM_WG1_OFF   (SM_WQK0_OFF + 608 * 8)
#define SM_WOUT_OFF  (SM_WG1_OFF + 1152 * 8)
#define SM_BG1_OFF   (SM_WOUT_OFF + 144 * 8)
#define SM_BOUT_OFF  (SM_BG1_OFF + 32 * 8)
#define SM_TOTAL     (SM_BOUT_OFF + 4 * 8)

__global__ void __launch_bounds__(128)
actor_main(const float* __restrict__ obs,
           const float* __restrict__ ca0p, const float* __restrict__ co0p,
           const float* __restrict__ ca1p, const float* __restrict__ co1p,
           float* __restrict__ out, int n)
{
    extern __shared__ __align__(16) unsigned char smbuf[];
    float* sObs  = (float*)smbuf;
    f2* sWqk0 = (f2*)(smbuf + SM_WQK0_OFF);
    f2* sWG1  = (f2*)(smbuf + SM_WG1_OFF);
    f2* sWout = (f2*)(smbuf + SM_WOUT_OFF);
    f2* sbG1  = (f2*)(smbuf + SM_BG1_OFF);
    f2* sbout = (f2*)(smbuf + SM_BOUT_OFF);

    int tid = threadIdx.x;

    {
        long nel = (long)n * 37;
        long eb  = (long)blockIdx.x * 9472;
        const float4* g4 = (const float4*)obs;
        float4* s4 = (float4*)sObs;
#pragma unroll 4
        for (int i = tid; i < 2368; i += 128) {
            long e = eb + (long)i * 4;
            if (e + 3 < nel) {
                s4[i] = g4[eb / 4 + i];
            } else {
#pragma unroll
                for (int k = 0; k < 4; k++)
                    sObs[i * 4 + k] = (e + k < nel) ? obs[e + k] : 0.f;
            }
        }
    }
    for (int i = tid; i < 608;  i += 128) { float w = g_Wqk0[i]; sWqk0[i] = mkf2(w, w); }
    for (int i = tid; i < 1152; i += 128) { float w = g_WG1[i];  sWG1[i]  = mkf2(w, w); }
    for (int i = tid; i < 144;  i += 128) { float w = g_Wout[i]; sWout[i] = mkf2(w, w); }
    if (tid < 32) { float w = g_bG1[tid];  sbG1[tid]  = mkf2(w, w); }
    if (tid < 4)  { float w = g_bout[tid]; sbout[tid] = mkf2(w, w); }
    __syncthreads();

    int r0 = blockIdx.x * 256 + tid;
    if (r0 >= n) return;
    int r1 = r0 + 128;
    const float* lo = &sObs[tid * 37];
    const float* hi = &sObs[(tid + 128) * 37];

    float nca0 = -__ldg(ca0p), nco0 = -__ldg(co0p);
    float nca1 = -__ldg(ca1p), nco1 = -__ldg(co1p);

    f2 nbv[2][7], obf[2][2], dnbv[7], dobf[2];
    f2 negone = mkf2(-1.f, -1.f);
#pragma unroll
    for (int k = 0; k < 2; k++) {
#pragma unroll
        for (int j = 0; j < 6; j++) nbv[k][j] = mkf2(lo[12 + 6 * k + j], hi[12 + 6 * k + j]);
        nbv[k][6] = mkf2(lo[24 + k], hi[24 + k]);
        obf[k][0] = mkf2(lo[26 + 2 * k], hi[26 + 2 * k]);
        obf[k][1] = mkf2(lo[27 + 2 * k], hi[27 + 2 * k]);
    }
#pragma unroll
    for (int j = 0; j < 7; j++) dnbv[j] = ffma2(nbv[1][j], negone, nbv[0][j]);
#pragma unroll
    for (int j = 0; j < 2; j++) dobf[j] = ffma2(obf[1][j], negone, obf[0][j]);

    float dAl[2], dAh[2], dOl[2], dOh[2];
    {
        float axl = lo[0], ayl = lo[1], axh = hi[0], ayh = hi[1];
#pragma unroll
        for (int k = 0; k < 2; k++) {
            float dx = axl - lo[12 + 6 * k], dy = ayl - lo[13 + 6 * k];
            dAl[k] = sqrtf(dx * dx + dy * dy);
            dx = axh - hi[12 + 6 * k]; dy = ayh - hi[13 + 6 * k];
            dAh[k] = sqrtf(dx * dx + dy * dy);
            dx = axl - lo[26 + 2 * k]; dy = ayl - lo[27 + 2 * k];
            dOl[k] = sqrtf(dx * dx + dy * dy);
            dx = axh - hi[26 + 2 * k]; dy = ayh - hi[27 + 2 * k];
            dOh[k] = sqrtf(dx * dx + dy * dy);
        }
    }
    f2 dwA0[2], dwO0[2], dwA1[2], dwO1[2];
#pragma unroll
    for (int k = 0; k < 2; k++) {
        dwA0[k] = mkf2(__expf(nca0 * dAl[k]), __expf(nca0 * dAh[k]));
        dwO0[k] = mkf2(__expf(nco0 * dOl[k]), __expf(nco0 * dOh[k]));
        dwA1[k] = mkf2(__expf(nca1 * dAl[k]), __expf(nca1 * dAh[k]));
        dwO1[k] = mkf2(__expf(nco1 * dOl[k]), __expf(nco1 * dOh[k]));
    }

    f2 G[32];
#pragma unroll
    for (int t = 0; t < 32; t++) G[t] = f2{0ull};
#pragma unroll
    for (int p = 0; p < 19; p++) {
        int src = (p < 12) ? p : p + 18;
        f2 q = mkf2(lo[src], hi[src]);
        const f2* row = sWqk0 + p * 32;
#pragma unroll
        for (int t = 0; t < 32; t += 2) {
            ulonglong2 wp = *(const ulonglong2*)(row + t);
            G[t]     = ffma2(q, f2{wp.x}, G[t]);
            G[t + 1] = ffma2(q, f2{wp.y}, G[t + 1]);
        }
    }

    f2 G1[32];
    attend_consume<32>(G, dwA0, dwO0, nbv, dnbv, obf, dobf, sWG1, sbG1, G1);

    f2 R[4];
    attend_consume<4>(G1, dwA1, dwO1, nbv, dnbv, obf, dobf, sWout, sbout, R);

    float o0l, o0h, o1l, o1h, o2l, o2h, o3l, o3h;
    unf2(R[0], o0l, o0h); unf2(R[1], o1l, o1h);
    unf2(R[2], o2l, o2h); unf2(R[3], o3l, o3h);
    ((float4*)out)[r0] = make_float4(o0l, o1l, o2l, o3l);
    if (r1 < n) ((float4*)out)[r1] = make_float4(o0h, o1h, o2h, o3h);
}

// ---------------- launch -----------------------------------------------------
extern "C" void kernel_launch(void* const* d_in, const int* in_sizes, int n_in,
                              void* d_out, int out_size)
{
    const float* obs   = (const float*)d_in[0];
    const float* wq0   = (const float*)d_in[1];
    const float* wak0  = (const float*)d_in[2];
    const float* wav0  = (const float*)d_in[3];
    const float* wok0  = (const float*)d_in[4];
    const float* wov0  = (const float*)d_in[5];
    const float* apw0  = (const float*)d_in[6];
    const float* apb0  = (const float*)d_in[7];
    const float* opw0  = (const float*)d_in[8];
    const float* opb0  = (const float*)d_in[9];
    const float* fpw0  = (const float*)d_in[10];
    const float* fpb0  = (const float*)d_in[11];
    const float* ca0   = (const float*)d_in[12];
    const float* co0   = (const float*)d_in[13];
    const float* wq1   = (const float*)d_in[14];
    const float* wak1  = (const float*)d_in[15];
    const float* wav1  = (const float*)d_in[16];
    const float* wok1  = (const float*)d_in[17];
    const float* wov1  = (const float*)d_in[18];
    const float* apw1  = (const float*)d_in[19];
    const float* apb1  = (const float*)d_in[20];
    const float* opw1  = (const float*)d_in[21];
    const float* opb1  = (const float*)d_in[22];
    const float* fpw1  = (const float*)d_in[23];
    const float* fpb1  = (const float*)d_in[24];
    const float* ca1   = (const float*)d_in[25];
    const float* co1   = (const float*)d_in[26];
    const float* headw = (const float*)d_in[27];
    const float* headb = (const float*)d_in[28];

    int n = in_sizes[0] / 37;

    pk1<<<149, 512>>>(wq0, wak0, wok0, wq1, wak1, wok1,
                      fpb0, apb0, opb0, fpb1, apb1, opb1, fpw0, fpw1);
    pk2<<<74, 512>>>(wav0, apw0, wov0, opw0, wav1, apw1, wov1, opw1,
                     fpw0, fpw1, headw, headb);

    cudaFuncSetAttribute(actor_main, cudaFuncAttributeMaxDynamicSharedMemorySize, SM_TOTAL);
    int grid = (n + 255) / 256;
    actor_main<<<grid, 128, SM_TOTAL>>>(obs, ca0, co0, ca1, co1, (float*)d_out, n);
}

// round 6
// speedup vs baseline: 1.7577x; 1.1087x over previous
#include <cuda_runtime.h>
#include <math.h>

// ---------------- folded-weight scratch (device globals) -------------------
__device__ float g_Wqk0[19 * 32];
__device__ float g_WG1[36 * 32];
__device__ float g_bG1[32];
__device__ float g_Wout[36 * 4];
__device__ float g_bout[4];

#define QK_SCALE 0.17677669529663687f   // 1/sqrt(32)

// ---------------- packed f32x2 helpers --------------------------------------
struct f2 { unsigned long long v; };

__device__ __forceinline__ f2 mkf2(float lo, float hi) {
    f2 r; asm("mov.b64 %0,{%1,%2};" : "=l"(r.v) : "f"(lo), "f"(hi)); return r;
}
__device__ __forceinline__ void unf2(f2 a, float& lo, float& hi) {
    asm("mov.b64 {%0,%1},%2;" : "=f"(lo), "=f"(hi) : "l"(a.v));
}
__device__ __forceinline__ f2 ffma2(f2 a, f2 b, f2 c) {
    f2 r; asm("fma.rn.f32x2 %0,%1,%2,%3;" : "=l"(r.v) : "l"(a.v), "l"(b.v), "l"(c.v)); return r;
}
__device__ __forceinline__ f2 fmul2(f2 a, f2 b) {
    f2 r; asm("mul.rn.f32x2 %0,%1,%2;" : "=l"(r.v) : "l"(a.v), "l"(b.v)); return r;
}
__device__ __forceinline__ float sigf(float d) {   // 1/(1+exp(-d))
    float e = __expf(-d);
    float r;
    asm("rcp.approx.f32 %0,%1;" : "=f"(r) : "f"(1.f + e));
    return r;
}

// ---------------- single precompute kernel ----------------------------------
// bid [0,19):  Wqk0 row p           (from wq0, wak0, wok0)
// bid [19,55): WG1 row t = bid-19   (T0 -> W0 -> X=W0@wq1 -> contract wk, scale)
// bid [55,91): Wout row t = bid-55  (T1 -> W  -> contract headw)
// bid 91:      bG1                  (b0 -> X=b0@wq1 -> contract wk, scale)
// bid 92:      bout                 (b1 -> contract headw + headb)
__global__ void __launch_bounds__(512, 1)
pk(const float* __restrict__ wq0,  const float* __restrict__ wak0,
   const float* __restrict__ wok0,
   const float* __restrict__ wq1,  const float* __restrict__ wak1,
   const float* __restrict__ wok1,
   const float* __restrict__ wav0, const float* __restrict__ apw0,
   const float* __restrict__ wov0, const float* __restrict__ opw0,
   const float* __restrict__ wav1, const float* __restrict__ apw1,
   const float* __restrict__ wov1, const float* __restrict__ opw1,
   const float* __restrict__ fpw0, const float* __restrict__ fpw1,
   const float* __restrict__ fpb0, const float* __restrict__ apb0,
   const float* __restrict__ opb0,
   const float* __restrict__ fpb1, const float* __restrict__ apb1,
   const float* __restrict__ opb1,
   const float* __restrict__ headw, const float* __restrict__ headb)
{
    __shared__ float sh[512];
    __shared__ float svec[128], sT[128], sW[128];
    __shared__ float sX[512];
    int bid = blockIdx.x, tid = threadIdx.x;

    if (bid < 19) {
        // ---- Wqk0 row p (scale folded) ----
        int p = bid;
        int t = tid >> 4, ci = tid & 15, h = t & 3;
        const float* wk; int j;
        if (t < 24) { wk = wak0; j = t >> 2; } else { wk = wok0; j = (t - 24) >> 2; }
        const float4* a4 = (const float4*)(wq0 + p * 512 + h * 128 + ci * 8);
        const float4* b4 = (const float4*)(wk + j * 512 + h * 128 + ci * 8);
        float4 a0 = a4[0], a1 = a4[1], b0 = b4[0], b1 = b4[1];
        float s = a0.x * b0.x + a0.y * b0.y + a0.z * b0.z + a0.w * b0.w
                + a1.x * b1.x + a1.y * b1.y + a1.z * b1.z + a1.w * b1.w;
#pragma unroll
        for (int off = 8; off; off >>= 1) s += __shfl_xor_sync(0xffffffffu, s, off);
        if (ci == 0) g_Wqk0[p * 32 + t] = s * QK_SCALE;
    } else if (bid < 91) {
        bool isW1 = (bid < 55);                 // WG1 (layer0 path) vs Wout (layer1 path)
        int t = isW1 ? bid - 19 : bid - 55;
        int h = t & 3;
        const float* wv; const float* pw; int j;
        if (isW1) {
            if (t < 28) { wv = wav0; pw = apw0; j = t >> 2; }
            else        { wv = wov0; pw = opw0; j = (t - 28) >> 2; }
        } else {
            if (t < 28) { wv = wav1; pw = apw1; j = t >> 2; }
            else        { wv = wov1; pw = opw1; j = (t - 28) >> 2; }
        }
        const float* fpw = isW1 ? fpw0 : fpw1;
        int q = tid >> 7, m = tid & 127;

        // ---- prefetch (one DRAM round) ----
        float pwv[32], fv[32];
        const float* baseT = pw + h * 16384 + q * 4096 + m;
        const float* baseW = fpw + (t < 28 ? 0 : 16384) + q * 4096 + m;
#pragma unroll
        for (int i = 0; i < 32; i++) pwv[i] = __ldg(baseT + i * 128);
#pragma unroll
        for (int i = 0; i < 32; i++) fv[i] = __ldg(baseW + i * 128);
        float4 hw = make_float4(0.f, 0.f, 0.f, 0.f);
        if (!isW1 && tid < 128) hw = *(const float4*)(headw + tid * 4);
        if (tid < 128) svec[tid] = wv[j * 512 + h * 128 + tid];
        __syncthreads();

        // ---- stage T ----
        float s = 0.f;
#pragma unroll
        for (int i = 0; i < 32; i++) s += svec[q * 32 + i] * pwv[i];
        sh[tid] = s;
        __syncthreads();
        if (tid < 128)
            sT[tid] = (sh[tid] + sh[tid + 128]) + (sh[tid + 256] + sh[tid + 384]);
        __syncthreads();

        // ---- stage W (= W0/W1 row over m) ----
        s = 0.f;
#pragma unroll
        for (int i = 0; i < 32; i++) s += sT[q * 32 + i] * fv[i];
        sh[tid] = s;
        __syncthreads();
        if (tid < 128)
            sW[tid] = (sh[tid] + sh[tid + 128]) + (sh[tid + 256] + sh[tid + 384]);
        __syncthreads();

        if (isW1) {
            // ---- stage X: X[c'] = sum_m sW[m] * wq1[m, c']  (c' = tid, coalesced)
            float xa[4] = {0.f, 0.f, 0.f, 0.f};
            const float* wqc = wq1 + tid;
#pragma unroll 32
            for (int mm = 0; mm < 128; mm++)
                xa[mm & 3] += sW[mm] * __ldg(wqc + mm * 512);
            sX[tid] = (xa[0] + xa[1]) + (xa[2] + xa[3]);
            __syncthreads();
            // ---- contract with wak1/wok1: WG1[t,t2] = scale * sum_c X[h2*128+c]*wk[j2,h2,c]
            int t2 = tid >> 4, ci = tid & 15, h2 = t2 & 3;
            const float* wk; int j2;
            if (t2 < 24) { wk = wak1; j2 = t2 >> 2; } else { wk = wok1; j2 = (t2 - 24) >> 2; }
            const float4* w4 = (const float4*)(wk + j2 * 512 + h2 * 128 + ci * 8);
            float4 wa = w4[0], wb = w4[1];
            const float* xs = sX + h2 * 128 + ci * 8;
            float s2 = xs[0] * wa.x + xs[1] * wa.y + xs[2] * wa.z + xs[3] * wa.w
                     + xs[4] * wb.x + xs[5] * wb.y + xs[6] * wb.z + xs[7] * wb.w;
#pragma unroll
            for (int off = 8; off; off >>= 1) s2 += __shfl_xor_sync(0xffffffffu, s2, off);
            if (ci == 0) g_WG1[t * 32 + t2] = s2 * QK_SCALE;
        } else {
            // ---- contract with headw: Wout[t,o] = sum_m sW[m]*headw[m,o]
            if (tid < 128) {
                float w0 = sW[tid];
                sh[tid]       = w0 * hw.x;
                sh[tid + 128] = w0 * hw.y;
                sh[tid + 256] = w0 * hw.z;
                sh[tid + 384] = w0 * hw.w;
            }
            __syncthreads();
            int w = tid >> 5, lane = tid & 31;
            if (w < 4) {
                float s2 = sh[w * 128 + lane] + sh[w * 128 + lane + 32]
                         + sh[w * 128 + lane + 64] + sh[w * 128 + lane + 96];
#pragma unroll
                for (int off = 16; off; off >>= 1) s2 += __shfl_xor_sync(0xffffffffu, s2, off);
                if (lane == 0) g_Wout[t * 4 + w] = s2;
            }
        }
    } else if (bid == 91) {
        // ---- bG1: b0 -> X -> contract wk, scale ----
        int q = tid >> 7, m = tid & 127;
        float fa[32], fo[32];
        const float* basea = fpw0 + q * 4096 + m;
        const float* baseo = fpw0 + 16384 + q * 4096 + m;
#pragma unroll
        for (int i = 0; i < 32; i++) fa[i] = __ldg(basea + i * 128);
#pragma unroll
        for (int i = 0; i < 32; i++) fo[i] = __ldg(baseo + i * 128);
        float s = 0.f;
#pragma unroll
        for (int i = 0; i < 32; i++) {
            int m1 = q * 32 + i;
            s += apb0[m1] * fa[i] + opb0[m1] * fo[i];
        }
        sh[tid] = s;
        __syncthreads();
        if (tid < 128)
            sW[tid] = fpb0[tid] + (sh[tid] + sh[tid + 128]) + (sh[tid + 256] + sh[tid + 384]);
        __syncthreads();
        float xa[4] = {0.f, 0.f, 0.f, 0.f};
        const float* wqc = wq1 + tid;
#pragma unroll 32
        for (int mm = 0; mm < 128; mm++)
            xa[mm & 3] += sW[mm] * __ldg(wqc + mm * 512);
        sX[tid] = (xa[0] + xa[1]) + (xa[2] + xa[3]);
        __syncthreads();
        int t2 = tid >> 4, ci = tid & 15, h2 = t2 & 3;
        const float* wk; int j2;
        if (t2 < 24) { wk = wak1; j2 = t2 >> 2; } else { wk = wok1; j2 = (t2 - 24) >> 2; }
        const float4* w4 = (const float4*)(wk + j2 * 512 + h2 * 128 + ci * 8);
        float4 wa = w4[0], wb = w4[1];
        const float* xs = sX + h2 * 128 + ci * 8;
        float s2 = xs[0] * wa.x + xs[1] * wa.y + xs[2] * wa.z + xs[3] * wa.w
                 + xs[4] * wb.x + xs[5] * wb.y + xs[6] * wb.z + xs[7] * wb.w;
#pragma unroll
        for (int off = 8; off; off >>= 1) s2 += __shfl_xor_sync(0xffffffffu, s2, off);
        if (ci == 0) g_bG1[t2] = s2 * QK_SCALE;
    } else {
        // ---- bout: b1 -> contract headw + headb ----
        int q = tid >> 7, m = tid & 127;
        float fa[32], fo[32];
        const float* basea = fpw1 + q * 4096 + m;
        const float* baseo = fpw1 + 16384 + q * 4096 + m;
#pragma unroll
        for (int i = 0; i < 32; i++) fa[i] = __ldg(basea + i * 128);
#pragma unroll
        for (int i = 0; i < 32; i++) fo[i] = __ldg(baseo + i * 128);
        float4 hw = make_float4(0.f, 0.f, 0.f, 0.f);
        if (tid < 128) hw = *(const float4*)(headw + tid * 4);
        float s = 0.f;
#pragma unroll
        for (int i = 0; i < 32; i++) {
            int m1 = q * 32 + i;
            s += apb1[m1] * fa[i] + opb1[m1] * fo[i];
        }
        sh[tid] = s;
        __syncthreads();
        if (tid < 128)
            sW[tid] = fpb1[tid] + (sh[tid] + sh[tid + 128]) + (sh[tid + 256] + sh[tid + 384]);
        __syncthreads();
        if (tid < 128) {
            float b = sW[tid];
            sh[tid]       = b * hw.x;
            sh[tid + 128] = b * hw.y;
            sh[tid + 256] = b * hw.z;
            sh[tid + 384] = b * hw.w;
        }
        __syncthreads();
        int w = tid >> 5, lane = tid & 31;
        if (w < 4) {
            float s2 = sh[w * 128 + lane] + sh[w * 128 + lane + 32]
                     + sh[w * 128 + lane + 64] + sh[w * 128 + lane + 96];
#pragma unroll
            for (int off = 16; off; off >>= 1) s2 += __shfl_xor_sync(0xffffffffu, s2, off);
            if (lane == 0) g_bout[w] = headb[w] + s2;
        }
    }
}

// ---------------- main per-row-pair kernel -----------------------------------
template <int W>
__device__ __forceinline__ void attend_consume(
    const f2 (&G)[32], const f2 (&dwA)[2], const f2 (&dwO)[2],
    const f2 (&nbv)[2][7], const f2 (&dnbv)[7],
    const f2 (&obf)[2][2], const f2 (&dobf)[2],
    const f2* __restrict__ wtab, const f2* __restrict__ bias, f2 (&ACC)[W])
{
    f2 lA[2][4], lO[2][4];
#pragma unroll
    for (int k = 0; k < 2; k++) {
#pragma unroll
        for (int h = 0; h < 4; h++) {
            f2 d = fmul2(nbv[k][0], G[h]);
#pragma unroll
            for (int j = 1; j < 6; j++) d = ffma2(nbv[k][j], G[j * 4 + h], d);
            lA[k][h] = fmul2(d, dwA[k]);
            f2 e = ffma2(obf[k][1], G[28 + h], fmul2(obf[k][0], G[24 + h]));
            lO[k][h] = fmul2(e, dwO[k]);
        }
    }
#pragma unroll
    for (int t = 0; t < W; t++) ACC[t] = bias[t];
#pragma unroll
    for (int h = 0; h < 4; h++) {
        {
            float l0l, l0h, l1l, l1h;
            unf2(lA[0][h], l0l, l0h); unf2(lA[1][h], l1l, l1h);
            f2 a0 = mkf2(sigf(l0l - l1l), sigf(l0h - l1h));
#pragma unroll
            for (int j = 0; j < 7; j++) {
                f2 uv = ffma2(a0, dnbv[j], nbv[1][j]);
                const f2* row = wtab + (j * 4 + h) * W;
#pragma unroll
                for (int t = 0; t < W; t += 2) {
                    ulonglong2 wp = *(const ulonglong2*)(row + t);
                    ACC[t]     = ffma2(uv, f2{wp.x}, ACC[t]);
                    ACC[t + 1] = ffma2(uv, f2{wp.y}, ACC[t + 1]);
                }
            }
        }
        {
            float l0l, l0h, l1l, l1h;
            unf2(lO[0][h], l0l, l0h); unf2(lO[1][h], l1l, l1h);
            f2 a0 = mkf2(sigf(l0l - l1l), sigf(l0h - l1h));
#pragma unroll
            for (int j = 0; j < 2; j++) {
                f2 uv = ffma2(a0, dobf[j], obf[1][j]);
                const f2* row = wtab + (28 + j * 4 + h) * W;
#pragma unroll
                for (int t = 0; t < W; t += 2) {
                    ulonglong2 wp = *(const ulonglong2*)(row + t);
                    ACC[t]     = ffma2(uv, f2{wp.x}, ACC[t]);
                    ACC[t + 1] = ffma2(uv, f2{wp.y}, ACC[t + 1]);
                }
            }
        }
    }
}

// dynamic smem layout (448 rows/block, 224 threads, 2 rows/thread)
#define MT           224
#define MROWS        448
#define SM_OBS_F     (MROWS * 37)              // 16576 floats
#define SM_OBS_B     (SM_OBS_F * 4)            // 66304 B
#define SM_WQK0_OFF  SM_OBS_B
#define SM_WG1_OFF   (SM_WQK0_OFF + 608 * 8)
#define SM_WOUT_OFF  (SM_WG1_OFF + 1152 * 8)
#define SM_BG1_OFF   (SM_WOUT_OFF + 144 * 8)
#define SM_BOUT_OFF  (SM_BG1_OFF + 32 * 8)
#define SM_TOTAL     (SM_BOUT_OFF + 4 * 8)     // 81824 B

__global__ void __launch_bounds__(MT)
actor_main(const float* __restrict__ obs,
           const float* __restrict__ ca0p, const float* __restrict__ co0p,
           const float* __restrict__ ca1p, const float* __restrict__ co1p,
           float* __restrict__ out, int n)
{
    extern __shared__ __align__(16) unsigned char smbuf[];
    float* sObs  = (float*)smbuf;
    f2* sWqk0 = (f2*)(smbuf + SM_WQK0_OFF);
    f2* sWG1  = (f2*)(smbuf + SM_WG1_OFF);
    f2* sWout = (f2*)(smbuf + SM_WOUT_OFF);
    f2* sbG1  = (f2*)(smbuf + SM_BG1_OFF);
    f2* sbout = (f2*)(smbuf + SM_BOUT_OFF);

    int tid = threadIdx.x;

    // ---- stage obs (independent of pk; overlaps it via PDL) ----
    {
        long nel = (long)n * 37;
        long eb  = (long)blockIdx.x * SM_OBS_F;
        const float4* g4 = (const float4*)obs;
        float4* s4 = (float4*)sObs;
#pragma unroll 4
        for (int i = tid; i < SM_OBS_F / 4; i += MT) {
            long e = eb + (long)i * 4;
            if (e + 3 < nel) {
                s4[i] = g4[eb / 4 + i];
            } else {
#pragma unroll
                for (int k = 0; k < 4; k++)
                    sObs[i * 4 + k] = (e + k < nel) ? obs[e + k] : 0.f;
            }
        }
    }

    // ---- wait for pk's global writes, then stage folded weights ----
    cudaGridDependencySynchronize();

    for (int i = tid; i < 608;  i += MT) { float w = g_Wqk0[i]; sWqk0[i] = mkf2(w, w); }
    for (int i = tid; i < 1152; i += MT) { float w = g_WG1[i];  sWG1[i]  = mkf2(w, w); }
    for (int i = tid; i < 144;  i += MT) { float w = g_Wout[i]; sWout[i] = mkf2(w, w); }
    if (tid < 32) { float w = g_bG1[tid];  sbG1[tid]  = mkf2(w, w); }
    if (tid < 4)  { float w = g_bout[tid]; sbout[tid] = mkf2(w, w); }
    __syncthreads();

    int r0 = blockIdx.x * MROWS + tid;
    if (r0 >= n) return;
    int r1 = r0 + MT;
    const float* lo = &sObs[tid * 37];
    const float* hi = &sObs[(tid + MT) * 37];

    float nca0 = -__ldg(ca0p), nco0 = -__ldg(co0p);
    float nca1 = -__ldg(ca1p), nco1 = -__ldg(co1p);

    f2 nbv[2][7], obf[2][2], dnbv[7], dobf[2];
    f2 negone = mkf2(-1.f, -1.f);
#pragma unroll
    for (int k = 0; k < 2; k++) {
#pragma unroll
        for (int j = 0; j < 6; j++) nbv[k][j] = mkf2(lo[12 + 6 * k + j], hi[12 + 6 * k + j]);
        nbv[k][6] = mkf2(lo[24 + k], hi[24 + k]);
        obf[k][0] = mkf2(lo[26 + 2 * k], hi[26 + 2 * k]);
        obf[k][1] = mkf2(lo[27 + 2 * k], hi[27 + 2 * k]);
    }
#pragma unroll
    for (int j = 0; j < 7; j++) dnbv[j] = ffma2(nbv[1][j], negone, nbv[0][j]);
#pragma unroll
    for (int j = 0; j < 2; j++) dobf[j] = ffma2(obf[1][j], negone, obf[0][j]);

    float dAl[2], dAh[2], dOl[2], dOh[2];
    {
        float axl = lo[0], ayl = lo[1], axh = hi[0], ayh = hi[1];
#pragma unroll
        for (int k = 0; k < 2; k++) {
            float dx = axl - lo[12 + 6 * k], dy = ayl - lo[13 + 6 * k];
            dAl[k] = sqrtf(dx * dx + dy * dy);
            dx = axh - hi[12 + 6 * k]; dy = ayh - hi[13 + 6 * k];
            dAh[k] = sqrtf(dx * dx + dy * dy);
            dx = axl - lo[26 + 2 * k]; dy = ayl - lo[27 + 2 * k];
            dOl[k] = sqrtf(dx * dx + dy * dy);
            dx = axh - hi[26 + 2 * k]; dy = ayh - hi[27 + 2 * k];
            dOh[k] = sqrtf(dx * dx + dy * dy);
        }
    }
    f2 dwA0[2], dwO0[2], dwA1[2], dwO1[2];
#pragma unroll
    for (int k = 0; k < 2; k++) {
        dwA0[k] = mkf2(__expf(nca0 * dAl[k]), __expf(nca0 * dAh[k]));
        dwO0[k] = mkf2(__expf(nco0 * dOl[k]), __expf(nco0 * dOh[k]));
        dwA1[k] = mkf2(__expf(nca1 * dAl[k]), __expf(nca1 * dAh[k]));
        dwO1[k] = mkf2(__expf(nco1 * dOl[k]), __expf(nco1 * dOh[k]));
    }

    f2 G[32];
#pragma unroll
    for (int t = 0; t < 32; t++) G[t] = f2{0ull};
#pragma unroll
    for (int p = 0; p < 19; p++) {
        int src = (p < 12) ? p : p + 18;
        f2 q = mkf2(lo[src], hi[src]);
        const f2* row = sWqk0 + p * 32;
#pragma unroll
        for (int t = 0; t < 32; t += 2) {
            ulonglong2 wp = *(const ulonglong2*)(row + t);
            G[t]     = ffma2(q, f2{wp.x}, G[t]);
            G[t + 1] = ffma2(q, f2{wp.y}, G[t + 1]);
        }
    }

    f2 G1[32];
    attend_consume<32>(G, dwA0, dwO0, nbv, dnbv, obf, dobf, sWG1, sbG1, G1);

    f2 R[4];
    attend_consume<4>(G1, dwA1, dwO1, nbv, dnbv, obf, dobf, sWout, sbout, R);

    float o0l, o0h, o1l, o1h, o2l, o2h, o3l, o3h;
    unf2(R[0], o0l, o0h); unf2(R[1], o1l, o1h);
    unf2(R[2], o2l, o2h); unf2(R[3], o3l, o3h);
    ((float4*)out)[r0] = make_float4(o0l, o1l, o2l, o3l);
    if (r1 < n) ((float4*)out)[r1] = make_float4(o0h, o1h, o2h, o3h);
}

// ---------------- launch -----------------------------------------------------
extern "C" void kernel_launch(void* const* d_in, const int* in_sizes, int n_in,
                              void* d_out, int out_size)
{
    const float* obs   = (const float*)d_in[0];
    const float* wq0   = (const float*)d_in[1];
    const float* wak0  = (const float*)d_in[2];
    const float* wav0  = (const float*)d_in[3];
    const float* wok0  = (const float*)d_in[4];
    const float* wov0  = (const float*)d_in[5];
    const float* apw0  = (const float*)d_in[6];
    const float* apb0  = (const float*)d_in[7];
    const float* opw0  = (const float*)d_in[8];
    const float* opb0  = (const float*)d_in[9];
    const float* fpw0  = (const float*)d_in[10];
    const float* fpb0  = (const float*)d_in[11];
    const float* ca0   = (const float*)d_in[12];
    const float* co0   = (const float*)d_in[13];
    const float* wq1   = (const float*)d_in[14];
    const float* wak1  = (const float*)d_in[15];
    const float* wav1  = (const float*)d_in[16];
    const float* wok1  = (const float*)d_in[17];
    const float* wov1  = (const float*)d_in[18];
    const float* apw1  = (const float*)d_in[19];
    const float* apb1  = (const float*)d_in[20];
    const float* opw1  = (const float*)d_in[21];
    const float* opb1  = (const float*)d_in[22];
    const float* fpw1  = (const float*)d_in[23];
    const float* fpb1  = (const float*)d_in[24];
    const float* ca1   = (const float*)d_in[25];
    const float* co1   = (const float*)d_in[26];
    const float* headw = (const float*)d_in[27];
    const float* headb = (const float*)d_in[28];

    int n = in_sizes[0] / 37;

    pk<<<93, 512>>>(wq0, wak0, wok0, wq1, wak1, wok1,
                    wav0, apw0, wov0, opw0, wav1, apw1, wov1, opw1,
                    fpw0, fpw1, fpb0, apb0, opb0, fpb1, apb1, opb1,
                    headw, headb);

    cudaFuncSetAttribute(actor_main, cudaFuncAttributeMaxDynamicSharedMemorySize, SM_TOTAL);

    int grid = (n + MROWS - 1) / MROWS;

    cudaLaunchConfig_t cfg = {};
    cfg.gridDim  = dim3((unsigned)grid, 1, 1);
    cfg.blockDim = dim3(MT, 1, 1);
    cfg.dynamicSmemBytes = SM_TOTAL;
    cfg.stream = 0;
    cudaLaunchAttribute attrs[1];
    attrs[0].id = cudaLaunchAttributeProgrammaticStreamSerialization;
    attrs[0].val.programmaticStreamSerializationAllowed = 1;
    cfg.attrs = attrs;
    cfg.numAttrs = 1;

    cudaLaunchKernelEx(&cfg, actor_main, obs, ca0, co0, ca1, co1, (float*)d_out, n);
}

// round 7
// speedup vs baseline: 1.9740x; 1.1231x over previous
#include <cuda_runtime.h>
#include <math.h>

// ---------------- folded-weight scratch (device globals) -------------------
__device__ float g_Wqk0[19 * 32];
__device__ float g_WG1[36 * 32];
__device__ float g_bG1[32];
__device__ float g_Wout[36 * 4];
__device__ float g_bout[4];

#define QK_SCALE 0.17677669529663687f   // 1/sqrt(32)

// ---------------- packed f32x2 helpers --------------------------------------
struct f2 { unsigned long long v; };

__device__ __forceinline__ f2 mkf2(float lo, float hi) {
    f2 r; asm("mov.b64 %0,{%1,%2};" : "=l"(r.v) : "f"(lo), "f"(hi)); return r;
}
__device__ __forceinline__ void unf2(f2 a, float& lo, float& hi) {
    asm("mov.b64 {%0,%1},%2;" : "=f"(lo), "=f"(hi) : "l"(a.v));
}
__device__ __forceinline__ f2 ffma2(f2 a, f2 b, f2 c) {
    f2 r; asm("fma.rn.f32x2 %0,%1,%2,%3;" : "=l"(r.v) : "l"(a.v), "l"(b.v), "l"(c.v)); return r;
}
__device__ __forceinline__ f2 fmul2(f2 a, f2 b) {
    f2 r; asm("mul.rn.f32x2 %0,%1,%2;" : "=l"(r.v) : "l"(a.v), "l"(b.v)); return r;
}
__device__ __forceinline__ float sigf(float d) {   // 1/(1+exp(-d))
    float e = __expf(-d);
    float r;
    asm("rcp.approx.f32 %0,%1;" : "=f"(r) : "f"(1.f + e));
    return r;
}

// ---------------- single precompute kernel ----------------------------------
__global__ void __launch_bounds__(512, 1)
pk(const float* __restrict__ wq0,  const float* __restrict__ wak0,
   const float* __restrict__ wok0,
   const float* __restrict__ wq1,  const float* __restrict__ wak1,
   const float* __restrict__ wok1,
   const float* __restrict__ wav0, const float* __restrict__ apw0,
   const float* __restrict__ wov0, const float* __restrict__ opw0,
   const float* __restrict__ wav1, const float* __restrict__ apw1,
   const float* __restrict__ wov1, const float* __restrict__ opw1,
   const float* __restrict__ fpw0, const float* __restrict__ fpw1,
   const float* __restrict__ fpb0, const float* __restrict__ apb0,
   const float* __restrict__ opb0,
   const float* __restrict__ fpb1, const float* __restrict__ apb1,
   const float* __restrict__ opb1,
   const float* __restrict__ headw, const float* __restrict__ headb)
{
    __shared__ float sh[512];
    __shared__ float svec[128], sT[128], sW[128];
    __shared__ float sX[512];
    int bid = blockIdx.x, tid = threadIdx.x;

    if (bid < 19) {
        int p = bid;
        int t = tid >> 4, ci = tid & 15, h = t & 3;
        const float* wk; int j;
        if (t < 24) { wk = wak0; j = t >> 2; } else { wk = wok0; j = (t - 24) >> 2; }
        const float4* a4 = (const float4*)(wq0 + p * 512 + h * 128 + ci * 8);
        const float4* b4 = (const float4*)(wk + j * 512 + h * 128 + ci * 8);
        float4 a0 = a4[0], a1 = a4[1], b0 = b4[0], b1 = b4[1];
        float s = a0.x * b0.x + a0.y * b0.y + a0.z * b0.z + a0.w * b0.w
                + a1.x * b1.x + a1.y * b1.y + a1.z * b1.z + a1.w * b1.w;
#pragma unroll
        for (int off = 8; off; off >>= 1) s += __shfl_xor_sync(0xffffffffu, s, off);
        if (ci == 0) g_Wqk0[p * 32 + t] = s * QK_SCALE;
    } else if (bid < 91) {
        bool isW1 = (bid < 55);
        int t = isW1 ? bid - 19 : bid - 55;
        int h = t & 3;
        const float* wv; const float* pw; int j;
        if (isW1) {
            if (t < 28) { wv = wav0; pw = apw0; j = t >> 2; }
            else        { wv = wov0; pw = opw0; j = (t - 28) >> 2; }
        } else {
            if (t < 28) { wv = wav1; pw = apw1; j = t >> 2; }
            else        { wv = wov1; pw = opw1; j = (t - 28) >> 2; }
        }
        const float* fpw = isW1 ? fpw0 : fpw1;
        int q = tid >> 7, m = tid & 127;

        float pwv[32], fv[32];
        const float* baseT = pw + h * 16384 + q * 4096 + m;
        const float* baseW = fpw + (t < 28 ? 0 : 16384) + q * 4096 + m;
#pragma unroll
        for (int i = 0; i < 32; i++) pwv[i] = __ldg(baseT + i * 128);
#pragma unroll
        for (int i = 0; i < 32; i++) fv[i] = __ldg(baseW + i * 128);
        float4 hw = make_float4(0.f, 0.f, 0.f, 0.f);
        if (!isW1 && tid < 128) hw = *(const float4*)(headw + tid * 4);
        if (tid < 128) svec[tid] = wv[j * 512 + h * 128 + tid];
        __syncthreads();

        float s = 0.f;
#pragma unroll
        for (int i = 0; i < 32; i++) s += svec[q * 32 + i] * pwv[i];
        sh[tid] = s;
        __syncthreads();
        if (tid < 128)
            sT[tid] = (sh[tid] + sh[tid + 128]) + (sh[tid + 256] + sh[tid + 384]);
        __syncthreads();

        s = 0.f;
#pragma unroll
        for (int i = 0; i < 32; i++) s += sT[q * 32 + i] * fv[i];
        sh[tid] = s;
        __syncthreads();
        if (tid < 128)
            sW[tid] = (sh[tid] + sh[tid + 128]) + (sh[tid + 256] + sh[tid + 384]);
        __syncthreads();

        if (isW1) {
            float xa[4] = {0.f, 0.f, 0.f, 0.f};
            const float* wqc = wq1 + tid;
#pragma unroll 32
            for (int mm = 0; mm < 128; mm++)
                xa[mm & 3] += sW[mm] * __ldg(wqc + mm * 512);
            sX[tid] = (xa[0] + xa[1]) + (xa[2] + xa[3]);
            __syncthreads();
            int t2 = tid >> 4, ci = tid & 15, h2 = t2 & 3;
            const float* wk; int j2;
            if (t2 < 24) { wk = wak1; j2 = t2 >> 2; } else { wk = wok1; j2 = (t2 - 24) >> 2; }
            const float4* w4 = (const float4*)(wk + j2 * 512 + h2 * 128 + ci * 8);
            float4 wa = w4[0], wb = w4[1];
            const float* xs = sX + h2 * 128 + ci * 8;
            float s2 = xs[0] * wa.x + xs[1] * wa.y + xs[2] * wa.z + xs[3] * wa.w
                     + xs[4] * wb.x + xs[5] * wb.y + xs[6] * wb.z + xs[7] * wb.w;
#pragma unroll
            for (int off = 8; off; off >>= 1) s2 += __shfl_xor_sync(0xffffffffu, s2, off);
            if (ci == 0) g_WG1[t * 32 + t2] = s2 * QK_SCALE;
        } else {
            if (tid < 128) {
                float w0 = sW[tid];
                sh[tid]       = w0 * hw.x;
                sh[tid + 128] = w0 * hw.y;
                sh[tid + 256] = w0 * hw.z;
                sh[tid + 384] = w0 * hw.w;
            }
            __syncthreads();
            int w = tid >> 5, lane = tid & 31;
            if (w < 4) {
                float s2 = sh[w * 128 + lane] + sh[w * 128 + lane + 32]
                         + sh[w * 128 + lane + 64] + sh[w * 128 + lane + 96];
#pragma unroll
                for (int off = 16; off; off >>= 1) s2 += __shfl_xor_sync(0xffffffffu, s2, off);
                if (lane == 0) g_Wout[t * 4 + w] = s2;
            }
        }
    } else if (bid == 91) {
        int q = tid >> 7, m = tid & 127;
        float fa[32], fo[32];
        const float* basea = fpw0 + q * 4096 + m;
        const float* baseo = fpw0 + 16384 + q * 4096 + m;
#pragma unroll
        for (int i = 0; i < 32; i++) fa[i] = __ldg(basea + i * 128);
#pragma unroll
        for (int i = 0; i < 32; i++) fo[i] = __ldg(baseo + i * 128);
        float s = 0.f;
#pragma unroll
        for (int i = 0; i < 32; i++) {
            int m1 = q * 32 + i;
            s += apb0[m1] * fa[i] + opb0[m1] * fo[i];
        }
        sh[tid] = s;
        __syncthreads();
        if (tid < 128)
            sW[tid] = fpb0[tid] + (sh[tid] + sh[tid + 128]) + (sh[tid + 256] + sh[tid + 384]);
        __syncthreads();
        float xa[4] = {0.f, 0.f, 0.f, 0.f};
        const float* wqc = wq1 + tid;
#pragma unroll 32
        for (int mm = 0; mm < 128; mm++)
            xa[mm & 3] += sW[mm] * __ldg(wqc + mm * 512);
        sX[tid] = (xa[0] + xa[1]) + (xa[2] + xa[3]);
        __syncthreads();
        int t2 = tid >> 4, ci = tid & 15, h2 = t2 & 3;
        const float* wk; int j2;
        if (t2 < 24) { wk = wak1; j2 = t2 >> 2; } else { wk = wok1; j2 = (t2 - 24) >> 2; }
        const float4* w4 = (const float4*)(wk + j2 * 512 + h2 * 128 + ci * 8);
        float4 wa = w4[0], wb = w4[1];
        const float* xs = sX + h2 * 128 + ci * 8;
        float s2 = xs[0] * wa.x + xs[1] * wa.y + xs[2] * wa.z + xs[3] * wa.w
                 + xs[4] * wb.x + xs[5] * wb.y + xs[6] * wb.z + xs[7] * wb.w;
#pragma unroll
        for (int off = 8; off; off >>= 1) s2 += __shfl_xor_sync(0xffffffffu, s2, off);
        if (ci == 0) g_bG1[t2] = s2 * QK_SCALE;
    } else {
        int q = tid >> 7, m = tid & 127;
        float fa[32], fo[32];
        const float* basea = fpw1 + q * 4096 + m;
        const float* baseo = fpw1 + 16384 + q * 4096 + m;
#pragma unroll
        for (int i = 0; i < 32; i++) fa[i] = __ldg(basea + i * 128);
#pragma unroll
        for (int i = 0; i < 32; i++) fo[i] = __ldg(baseo + i * 128);
        float4 hw = make_float4(0.f, 0.f, 0.f, 0.f);
        if (tid < 128) hw = *(const float4*)(headw + tid * 4);
        float s = 0.f;
#pragma unroll
        for (int i = 0; i < 32; i++) {
            int m1 = q * 32 + i;
            s += apb1[m1] * fa[i] + opb1[m1] * fo[i];
        }
        sh[tid] = s;
        __syncthreads();
        if (tid < 128)
            sW[tid] = fpb1[tid] + (sh[tid] + sh[tid + 128]) + (sh[tid + 256] + sh[tid + 384]);
        __syncthreads();
        if (tid < 128) {
            float b = sW[tid];
            sh[tid]       = b * hw.x;
            sh[tid + 128] = b * hw.y;
            sh[tid + 256] = b * hw.z;
            sh[tid + 384] = b * hw.w;
        }
        __syncthreads();
        int w = tid >> 5, lane = tid & 31;
        if (w < 4) {
            float s2 = sh[w * 128 + lane] + sh[w * 128 + lane + 32]
                     + sh[w * 128 + lane + 64] + sh[w * 128 + lane + 96];
#pragma unroll
            for (int off = 16; off; off >>= 1) s2 += __shfl_xor_sync(0xffffffffu, s2, off);
            if (lane == 0) g_bout[w] = headb[w] + s2;
        }
    }
}

// ---------------- main per-row-pair kernel -----------------------------------
template <int W>
__device__ __forceinline__ void attend_consume(
    const f2 (&G)[32], const f2 (&dwA)[2], const f2 (&dwO)[2],
    const f2 (&nbv)[2][7], const f2 (&dnbv)[7],
    const f2 (&obf)[2][2], const f2 (&dobf)[2],
    const f2* __restrict__ wtab, const f2* __restrict__ bias, f2 (&ACC)[W])
{
    // logits (G dies after this block)
    f2 sA[4], sO[4];
#pragma unroll
    for (int h = 0; h < 4; h++) {
        f2 l0, l1;
        {
            f2 d0 = fmul2(nbv[0][0], G[h]);
            f2 d1 = fmul2(nbv[1][0], G[h]);
#pragma unroll
            for (int j = 1; j < 6; j++) {
                d0 = ffma2(nbv[0][j], G[j * 4 + h], d0);
                d1 = ffma2(nbv[1][j], G[j * 4 + h], d1);
            }
            l0 = fmul2(d0, dwA[0]);
            l1 = fmul2(d1, dwA[1]);
        }
        float a, b, c, d;
        unf2(l0, a, b); unf2(l1, c, d);
        sA[h] = mkf2(sigf(a - c), sigf(b - d));
        {
            f2 e0 = ffma2(obf[0][1], G[28 + h], fmul2(obf[0][0], G[24 + h]));
            f2 e1 = ffma2(obf[1][1], G[28 + h], fmul2(obf[1][0], G[24 + h]));
            l0 = fmul2(e0, dwO[0]);
            l1 = fmul2(e1, dwO[1]);
        }
        unf2(l0, a, b); unf2(l1, c, d);
        sO[h] = mkf2(sigf(a - c), sigf(b - d));
    }
#pragma unroll
    for (int t = 0; t < W; t++) ACC[t] = bias[t];
#pragma unroll
    for (int h = 0; h < 4; h++) {
#pragma unroll
        for (int j = 0; j < 7; j++) {
            f2 uv = ffma2(sA[h], dnbv[j], nbv[1][j]);
            const f2* row = wtab + (j * 4 + h) * W;
#pragma unroll
            for (int t = 0; t < W; t += 2) {
                ulonglong2 wp = *(const ulonglong2*)(row + t);
                ACC[t]     = ffma2(uv, f2{wp.x}, ACC[t]);
                ACC[t + 1] = ffma2(uv, f2{wp.y}, ACC[t + 1]);
            }
        }
#pragma unroll
        for (int j = 0; j < 2; j++) {
            f2 uv = ffma2(sO[h], dobf[j], obf[1][j]);
            const f2* row = wtab + (28 + j * 4 + h) * W;
#pragma unroll
            for (int t = 0; t < W; t += 2) {
                ulonglong2 wp = *(const ulonglong2*)(row + t);
                ACC[t]     = ffma2(uv, f2{wp.x}, ACC[t]);
                ACC[t + 1] = ffma2(uv, f2{wp.y}, ACC[t + 1]);
            }
        }
    }
}

// dynamic smem layout (448 rows/block, 224 threads, 2 rows/thread)
#define MT           224
#define MROWS        448
#define SM_OBS_F     (MROWS * 37)
#define SM_OBS_B     (SM_OBS_F * 4)
#define SM_WQK0_OFF  SM_OBS_B
#define SM_WG1_OFF   (SM_WQK0_OFF + 608 * 8)
#define SM_WOUT_OFF  (SM_WG1_OFF + 1152 * 8)
#define SM_BG1_OFF   (SM_WOUT_OFF + 144 * 8)
#define SM_BOUT_OFF  (SM_BG1_OFF + 32 * 8)
#define SM_TOTAL     (SM_BOUT_OFF + 4 * 8)

__global__ void __launch_bounds__(MT, 2)
actor_main(const float* __restrict__ obs,
           const float* __restrict__ ca0p, const float* __restrict__ co0p,
           const float* __restrict__ ca1p, const float* __restrict__ co1p,
           float* __restrict__ out, int n)
{
    extern __shared__ __align__(16) unsigned char smbuf[];
    float* sObs  = (float*)smbuf;
    f2* sWqk0 = (f2*)(smbuf + SM_WQK0_OFF);
    f2* sWG1  = (f2*)(smbuf + SM_WG1_OFF);
    f2* sWout = (f2*)(smbuf + SM_WOUT_OFF);
    f2* sbG1  = (f2*)(smbuf + SM_BG1_OFF);
    f2* sbout = (f2*)(smbuf + SM_BOUT_OFF);

    int tid = threadIdx.x;

    // ---- stage obs (independent of pk; overlaps it via PDL) ----
    {
        long nel = (long)n * 37;
        long eb  = (long)blockIdx.x * SM_OBS_F;
        const float4* g4 = (const float4*)obs;
        float4* s4 = (float4*)sObs;
#pragma unroll 4
        for (int i = tid; i < SM_OBS_F / 4; i += MT) {
            long e = eb + (long)i * 4;
            if (e + 3 < nel) {
                s4[i] = g4[eb / 4 + i];
            } else {
#pragma unroll
                for (int k = 0; k < 4; k++)
                    sObs[i * 4 + k] = (e + k < nel) ? obs[e + k] : 0.f;
            }
        }
    }

    cudaGridDependencySynchronize();

    for (int i = tid; i < 608;  i += MT) { float w = g_Wqk0[i]; sWqk0[i] = mkf2(w, w); }
    for (int i = tid; i < 1152; i += MT) { float w = g_WG1[i];  sWG1[i]  = mkf2(w, w); }
    for (int i = tid; i < 144;  i += MT) { float w = g_Wout[i]; sWout[i] = mkf2(w, w); }
    if (tid < 32) { float w = g_bG1[tid];  sbG1[tid]  = mkf2(w, w); }
    if (tid < 4)  { float w = g_bout[tid]; sbout[tid] = mkf2(w, w); }
    __syncthreads();

    int r0 = blockIdx.x * MROWS + tid;
    if (r0 >= n) return;
    int r1 = r0 + MT;
    const float* lo = &sObs[tid * 37];
    const float* hi = &sObs[(tid + MT) * 37];

    f2 nbv[2][7], obf[2][2], dnbv[7], dobf[2];
    f2 negone = mkf2(-1.f, -1.f);
#pragma unroll
    for (int k = 0; k < 2; k++) {
#pragma unroll
        for (int j = 0; j < 6; j++) nbv[k][j] = mkf2(lo[12 + 6 * k + j], hi[12 + 6 * k + j]);
        nbv[k][6] = mkf2(lo[24 + k], hi[24 + k]);
        obf[k][0] = mkf2(lo[26 + 2 * k], hi[26 + 2 * k]);
        obf[k][1] = mkf2(lo[27 + 2 * k], hi[27 + 2 * k]);
    }
#pragma unroll
    for (int j = 0; j < 7; j++) dnbv[j] = ffma2(nbv[1][j], negone, nbv[0][j]);
#pragma unroll
    for (int j = 0; j < 2; j++) dobf[j] = ffma2(obf[1][j], negone, obf[0][j]);

    // distances (kept as 8 scalars; per-layer decay computed just before use)
    float dAl[2], dAh[2], dOl[2], dOh[2];
    {
        float axl = lo[0], ayl = lo[1], axh = hi[0], ayh = hi[1];
#pragma unroll
        for (int k = 0; k < 2; k++) {
            float dx = axl - lo[12 + 6 * k], dy = ayl - lo[13 + 6 * k];
            dAl[k] = sqrtf(dx * dx + dy * dy);
            dx = axh - hi[12 + 6 * k]; dy = ayh - hi[13 + 6 * k];
            dAh[k] = sqrtf(dx * dx + dy * dy);
            dx = axl - lo[26 + 2 * k]; dy = ayl - lo[27 + 2 * k];
            dOl[k] = sqrtf(dx * dx + dy * dy);
            dx = axh - hi[26 + 2 * k]; dy = ayh - hi[27 + 2 * k];
            dOh[k] = sqrtf(dx * dx + dy * dy);
        }
    }

    // ---- layer-0 logit features: G0 = qf @ Wqk0 ----
    f2 G[32];
#pragma unroll
    for (int t = 0; t < 32; t++) G[t] = f2{0ull};
#pragma unroll
    for (int p = 0; p < 19; p++) {
        int src = (p < 12) ? p : p + 18;
        f2 q = mkf2(lo[src], hi[src]);
        const f2* row = sWqk0 + p * 32;
#pragma unroll
        for (int t = 0; t < 32; t += 2) {
            ulonglong2 wp = *(const ulonglong2*)(row + t);
            G[t]     = ffma2(q, f2{wp.x}, G[t]);
            G[t + 1] = ffma2(q, f2{wp.y}, G[t + 1]);
        }
    }

    f2 G1[32];
    {
        float nca0 = -__ldg(ca0p), nco0 = -__ldg(co0p);
        f2 dwA0[2], dwO0[2];
#pragma unroll
        for (int k = 0; k < 2; k++) {
            dwA0[k] = mkf2(__expf(nca0 * dAl[k]), __expf(nca0 * dAh[k]));
            dwO0[k] = mkf2(__expf(nco0 * dOl[k]), __expf(nco0 * dOh[k]));
        }
        attend_consume<32>(G, dwA0, dwO0, nbv, dnbv, obf, dobf, sWG1, sbG1, G1);
    }

    f2 R[4];
    {
        float nca1 = -__ldg(ca1p), nco1 = -__ldg(co1p);
        f2 dwA1[2], dwO1[2];
#pragma unroll
        for (int k = 0; k < 2; k++) {
            dwA1[k] = mkf2(__expf(nca1 * dAl[k]), __expf(nca1 * dAh[k]));
            dwO1[k] = mkf2(__expf(nco1 * dOl[k]), __expf(nco1 * dOh[k]));
        }
        attend_consume<4>(G1, dwA1, dwO1, nbv, dnbv, obf, dobf, sWout, sbout, R);
    }

    float o0l, o0h, o1l, o1h, o2l, o2h, o3l, o3h;
    unf2(R[0], o0l, o0h); unf2(R[1], o1l, o1h);
    unf2(R[2], o2l, o2h); unf2(R[3], o3l, o3h);
    ((float4*)out)[r0] = make_float4(o0l, o1l, o2l, o3l);
    if (r1 < n) ((float4*)out)[r1] = make_float4(o0h, o1h, o2h, o3h);
}

// ---------------- launch -----------------------------------------------------
extern "C" void kernel_launch(void* const* d_in, const int* in_sizes, int n_in,
                              void* d_out, int out_size)
{
    const float* obs   = (const float*)d_in[0];
    const float* wq0   = (const float*)d_in[1];
    const float* wak0  = (const float*)d_in[2];
    const float* wav0  = (const float*)d_in[3];
    const float* wok0  = (const float*)d_in[4];
    const float* wov0  = (const float*)d_in[5];
    const float* apw0  = (const float*)d_in[6];
    const float* apb0  = (const float*)d_in[7];
    const float* opw0  = (const float*)d_in[8];
    const float* opb0  = (const float*)d_in[9];
    const float* fpw0  = (const float*)d_in[10];
    const float* fpb0  = (const float*)d_in[11];
    const float* ca0   = (const float*)d_in[12];
    const float* co0   = (const float*)d_in[13];
    const float* wq1   = (const float*)d_in[14];
    const float* wak1  = (const float*)d_in[15];
    const float* wav1  = (const float*)d_in[16];
    const float* wok1  = (const float*)d_in[17];
    const float* wov1  = (const float*)d_in[18];
    const float* apw1  = (const float*)d_in[19];
    const float* apb1  = (const float*)d_in[20];
    const float* opw1  = (const float*)d_in[21];
    const float* opb1  = (const float*)d_in[22];
    const float* fpw1  = (const float*)d_in[23];
    const float* fpb1  = (const float*)d_in[24];
    const float* ca1   = (const float*)d_in[25];
    const float* co1   = (const float*)d_in[26];
    const float* headw = (const float*)d_in[27];
    const float* headb = (const float*)d_in[28];

    int n = in_sizes[0] / 37;

    pk<<<93, 512>>>(wq0, wak0, wok0, wq1, wak1, wok1,
                    wav0, apw0, wov0, opw0, wav1, apw1, wov1, opw1,
                    fpw0, fpw1, fpb0, apb0, opb0, fpb1, apb1, opb1,
                    headw, headb);

    cudaFuncSetAttribute(actor_main, cudaFuncAttributeMaxDynamicSharedMemorySize, SM_TOTAL);

    int grid = (n + MROWS - 1) / MROWS;

    cudaLaunchConfig_t cfg = {};
    cfg.gridDim  = dim3((unsigned)grid, 1, 1);
    cfg.blockDim = dim3(MT, 1, 1);
    cfg.dynamicSmemBytes = SM_TOTAL;
    cfg.stream = 0;
    cudaLaunchAttribute attrs[1];
    attrs[0].id = cudaLaunchAttributeProgrammaticStreamSerialization;
    attrs[0].val.programmaticStreamSerializationAllowed = 1;
    cfg.attrs = attrs;
    cfg.numAttrs = 1;

    cudaLaunchKernelEx(&cfg, actor_main, obs, ca0, co0, ca1, co1, (float*)d_out, n);
}